// round 15
// baseline (speedup 1.0000x reference)
#include <cuda_runtime.h>
#include <cuda_fp16.h>
#include <math.h>
#include <stdint.h>

#define Bq 4
#define Tt 1024
#define Cc 768
#define Hh 12
#define Dd 64
#define Ll 12
#define BT 4096

typedef __half f16;

// ---------------- scratch (device globals) ------------------------------------
__device__ __align__(16) float g_x[BT * Cc];
__device__ __align__(16) f16 g_qkv16[BT * 3 * Cc];

__device__ __align__(16) f16 g_hh[BT * Cc];
__device__ __align__(16) f16 g_hl[BT * Cc];
__device__ __align__(16) f16 g_yh[BT * Cc];
__device__ __align__(16) f16 g_yl[BT * Cc];
__device__ __align__(16) f16 g_ffh[BT * 4 * Cc];
__device__ __align__(16) f16 g_ffl[BT * 4 * Cc];

__device__ __align__(16) f16 g_wqkvT[Ll * 3 * Cc * Cc];
__device__ __align__(16) f16 g_waoT[Ll * Cc * Cc];
__device__ __align__(16) f16 g_wfcT[Ll * 4 * Cc * Cc];
__device__ __align__(16) f16 g_wfpT[Ll * Cc * 4 * Cc];

// ---------------- helpers -----------------------------------------------------
__device__ __forceinline__ uint32_t smem_u32(const void* p) {
    uint32_t a;
    asm("{ .reg .u64 t; cvta.to.shared.u64 t, %1; cvt.u32.u64 %0, t; }"
        : "=r"(a) : "l"(p));
    return a;
}
__device__ __forceinline__ void ldsm4(uint32_t* r, uint32_t addr) {
    asm volatile("ldmatrix.sync.aligned.m8n8.x4.shared.b16 {%0,%1,%2,%3}, [%4];"
                 : "=r"(r[0]), "=r"(r[1]), "=r"(r[2]), "=r"(r[3]) : "r"(addr));
}
__device__ __forceinline__ void ldsm4t(uint32_t* r, uint32_t addr) {
    asm volatile("ldmatrix.sync.aligned.m8n8.x4.trans.shared.b16 {%0,%1,%2,%3}, [%4];"
                 : "=r"(r[0]), "=r"(r[1]), "=r"(r[2]), "=r"(r[3]) : "r"(addr));
}
__device__ __forceinline__ void cp16(uint32_t dst, const void* src) {
    asm volatile("cp.async.ca.shared.global [%0], [%1], 16;"
                 :: "r"(dst), "l"(src) : "memory");
}
__device__ __forceinline__ void cp16b(uint32_t dst, const void* src) {
    asm volatile("cp.async.ca.shared.global.L2::256B [%0], [%1], 16;"
                 :: "r"(dst), "l"(src) : "memory");
}
__device__ __forceinline__ void cp_commit() {
    asm volatile("cp.async.commit_group;" ::: "memory");
}
__device__ __forceinline__ void mma16(float* c, const uint32_t* a,
                                      uint32_t b0, uint32_t b1) {
    asm volatile(
        "mma.sync.aligned.m16n8k16.row.col.f32.f16.f16.f32 "
        "{%0,%1,%2,%3}, {%4,%5,%6,%7}, {%8,%9}, {%0,%1,%2,%3};"
        : "+f"(c[0]), "+f"(c[1]), "+f"(c[2]), "+f"(c[3])
        : "r"(a[0]), "r"(a[1]), "r"(a[2]), "r"(a[3]), "r"(b0), "r"(b1));
}
__device__ __forceinline__ void split2(float f, f16& h, f16& l) {
    h = __float2half_rn(f);
    l = __float2half_rn(f - __half2float(h));
}
__device__ __forceinline__ float gelu_f(float x) {
    float x3 = x * x * x;
    return 0.5f * x * (1.f + tanhf(0.7978845608028654f * (x + 0.044715f * x3)));
}
__device__ __forceinline__ uint32_t packh2(float a, float b) {
    __half2 h = __floats2half2_rn(a, b);
    return *(uint32_t*)&h;
}

// ---------------- weight transpose to fp16 (all 4 weights, one launch) ---------
#define WS_QKV 20736
#define WS_AO  (WS_QKV + 6912)
#define WS_FC  (WS_AO + 27648)
#define WS_ALL (WS_FC + 27648)

__global__ void wsplit_all(const float* __restrict__ wqkv, const float* __restrict__ wao,
                           const float* __restrict__ wfc, const float* __restrict__ wfp,
                           f16* __restrict__ tqkv, f16* __restrict__ tao,
                           f16* __restrict__ tfc, f16* __restrict__ tfp) {
    __shared__ float t[32][33];
    int bid = blockIdx.x;
    const float* W;
    f16* T;
    int K, N, nx, base;
    if (bid < WS_QKV)     { W = wqkv; T = tqkv; K = Cc;     N = 3 * Cc; nx = 72; base = bid; }
    else if (bid < WS_AO) { W = wao;  T = tao;  K = Cc;     N = Cc;     nx = 24; base = bid - WS_QKV; }
    else if (bid < WS_FC) { W = wfc;  T = tfc;  K = Cc;     N = 4 * Cc; nx = 96; base = bid - WS_AO; }
    else                  { W = wfp;  T = tfp;  K = 4 * Cc; N = Cc;     nx = 24; base = bid - WS_FC; }
    int per_layer = nx * (K >> 5);
    int layer = base / per_layer;
    int rem = base - layer * per_layer;
    int bx = rem % nx, by = rem / nx;
    size_t loff = (size_t)layer * K * N;
    const float* Wl = W + loff;
    f16* Tl = T + loff;
    int n0 = bx * 32, k0 = by * 32;
    int tx = threadIdx.x & 31, ty = threadIdx.x >> 5;
#pragma unroll
    for (int j = 0; j < 4; j++)
        t[ty + 8 * j][tx] = Wl[(size_t)(k0 + ty + 8 * j) * N + n0 + tx];
    __syncthreads();
#pragma unroll
    for (int j = 0; j < 4; j++) {
        int nr = ty + 8 * j;
        Tl[(size_t)(n0 + nr) * K + k0 + tx] = __float2half_rn(t[tx][nr]);
    }
}

// ---------------- embedding ---------------------------------------------------
__global__ void embed_kernel(const int* __restrict__ idx, const float* __restrict__ wte,
                             const float* __restrict__ wpe, float* __restrict__ x) {
    int row = blockIdx.x;
    int tok = idx[row];
    int t = row & (Tt - 1);
    int c = threadIdx.x * 4;
    float4 a = *(const float4*)(wte + (size_t)tok * Cc + c);
    float4 p = *(const float4*)(wpe + (size_t)t * Cc + c);
    a.x += p.x; a.y += p.y; a.z += p.z; a.w += p.w;
    *(float4*)(x + (size_t)row * Cc + c) = a;
}

// ---------------- layernorm (fp32 in, hi/lo fp16 out) -- 192 thr, float4 -------
__global__ void ln_kernel(const float* __restrict__ in, const float* __restrict__ w,
                          const float* __restrict__ b, f16* __restrict__ oh,
                          f16* __restrict__ ol) {
    int row = blockIdx.x;
    int t = threadIdx.x;   // 0..191
    float4 v = *(const float4*)(in + (size_t)row * Cc + t * 4);
    float s = v.x + v.y + v.z + v.w;
    float s2 = v.x * v.x + v.y * v.y + v.z * v.z + v.w * v.w;
#pragma unroll
    for (int m = 16; m; m >>= 1) {
        s  += __shfl_xor_sync(0xffffffffu, s, m);
        s2 += __shfl_xor_sync(0xffffffffu, s2, m);
    }
    __shared__ float rs[6], rs2[6];
    if ((t & 31) == 0) { rs[t >> 5] = s; rs2[t >> 5] = s2; }
    __syncthreads();
    s = 0.f; s2 = 0.f;
#pragma unroll
    for (int i = 0; i < 6; i++) { s += rs[i]; s2 += rs2[i]; }
    float mu = s * (1.0f / Cc);
    float var = s2 * (1.0f / Cc) - mu * mu;
    float rstd = rsqrtf(var + 1e-5f);
    float4 wv = *(const float4*)(w + t * 4);
    float4 bv = *(const float4*)(b + t * 4);
    float o0 = (v.x - mu) * rstd * wv.x + bv.x;
    float o1 = (v.y - mu) * rstd * wv.y + bv.y;
    float o2 = (v.z - mu) * rstd * wv.z + bv.z;
    float o3 = (v.w - mu) * rstd * wv.w + bv.w;
    f16 h0, l0, h1, l1, h2, l2, h3, l3;
    split2(o0, h0, l0); split2(o1, h1, l1); split2(o2, h2, l2); split2(o3, h3, l3);
    __half2 hA, hB, lA, lB;
    hA.x = h0; hA.y = h1; hB.x = h2; hB.y = h3;
    lA.x = l0; lA.y = l1; lB.x = l2; lB.y = l3;
    size_t off = (size_t)row * Cc + t * 4;
    *(__half2*)(oh + off) = hA;
    *(__half2*)(oh + off + 2) = hB;
    *(__half2*)(ol + off) = lA;
    *(__half2*)(ol + off + 2) = lB;
}

// ---------------- shared GEMM pieces -------------------------------------------
#define SAW 20

template <bool GELU, bool RES, int OUTM, int NJ>
__device__ __forceinline__ void gemm_epilogue(
    float acc[2][2 * NJ][4], int m0, int n0, int wm, int wn, int g, int c,
    const float* __restrict__ bias, const float* __restrict__ res,
    float* __restrict__ outf, f16* __restrict__ outh, f16* __restrict__ outl, int N) {
#pragma unroll
    for (int mt = 0; mt < 2; mt++) {
        int rbase = m0 + wm * 32 + mt * 16 + g;
#pragma unroll
        for (int nt = 0; nt < 2 * NJ; nt++) {
            int col = n0 + wn * (NJ * 16) + nt * 8 + 2 * c;
            float b0v = bias[col], b1v = bias[col + 1];
#pragma unroll
            for (int rr = 0; rr < 2; rr++) {
                int r = rbase + rr * 8;
                float v0 = acc[mt][nt][rr * 2 + 0] + b0v;
                float v1 = acc[mt][nt][rr * 2 + 1] + b1v;
                if (GELU) { v0 = gelu_f(v0); v1 = gelu_f(v1); }
                if (RES) {
                    float2 rv = *(const float2*)(res + (size_t)r * N + col);
                    v0 += rv.x;
                    v1 += rv.y;
                }
                if (OUTM == 0) {
                    float2 ov; ov.x = v0; ov.y = v1;
                    *(float2*)(outf + (size_t)r * N + col) = ov;
                } else if (OUTM == 1) {
                    uint32_t hv = packh2(v0, v1);
                    *(uint32_t*)(outh + (size_t)r * N + col) = hv;
                } else {
                    f16 h0, l0, h1, l1;
                    split2(v0, h0, l0);
                    split2(v1, h1, l1);
                    __half2 hv; hv.x = h0; hv.y = h1;
                    __half2 lv; lv.x = l0; lv.y = l1;
                    *(__half2*)(outh + (size_t)r * N + col) = hv;
                    *(__half2*)(outl + (size_t)r * N + col) = lv;
                }
            }
        }
    }
}

// one k-tile; B-fragment loads software-pipelined one jj ahead (R14-proven).
template <int NJ>
__device__ __forceinline__ void gemm_ktile(
    float acc[2][2 * NJ][4], uint32_t abase, uint32_t bbase, uint32_t offAL) {
#pragma unroll
    for (int ks = 0; ks < 2; ks++) {
        uint32_t ah[2][4], al[2][4];
#pragma unroll
        for (int mt = 0; mt < 2; mt++) {
            uint32_t ar = abase + (uint32_t)(mt * 16) * SAW * 4 + ks * 32;
            ldsm4(ah[mt], ar);
            ldsm4(al[mt], ar + offAL);
        }
        uint32_t bf[4];
        ldsm4(bf, bbase + ks * 32);
#pragma unroll
        for (int jj = 0; jj < NJ; jj++) {
            uint32_t bfn[4];
            if (jj + 1 < NJ)
                ldsm4(bfn, bbase + (uint32_t)((jj + 1) * 16) * SAW * 4 + ks * 32);
#pragma unroll
            for (int mt = 0; mt < 2; mt++) {
                mma16(acc[mt][2 * jj], ah[mt], bf[0], bf[1]);
                mma16(acc[mt][2 * jj], al[mt], bf[0], bf[1]);
                mma16(acc[mt][2 * jj + 1], ah[mt], bf[2], bf[3]);
                mma16(acc[mt][2 * jj + 1], al[mt], bf[2], bf[3]);
            }
            if (jj + 1 < NJ) {
                bf[0] = bfn[0]; bf[1] = bfn[1]; bf[2] = bfn[2]; bf[3] = bfn[3];
            }
        }
    }
}

// ---------------- GEMM 128x128 (256 thr, 3-stage) ------------------------------
#define OFF_AL1 10240u
#define OFF_B1  20480u
#define BUFSZ1  30720u
#define GSM1    (3 * 30720)

template <bool GELU, bool RES, int OUTM>
__global__ void __launch_bounds__(256, 2) gemm_mma(
    const f16* __restrict__ Ah, const f16* __restrict__ Al,
    const f16* __restrict__ B,
    const float* __restrict__ bias, const float* __restrict__ res,
    float* __restrict__ outf, f16* __restrict__ outh, f16* __restrict__ outl,
    int M, int N, int K) {
    extern __shared__ char smem[];
    const uint32_t sb = smem_u32(smem);
    const int tid = threadIdx.x;
    const int lane = tid & 31, wid = tid >> 5;
    const int g = lane >> 2, c = lane & 3;
    const int wm = wid & 3, wn = wid >> 2;
    const int m0 = blockIdx.y * 128, n0 = blockIdx.x * 128;

    const int r_ld = tid >> 2;
    const int q_ld = tid & 3;
    const uint32_t d0 = (uint32_t)(r_ld * SAW + q_ld * 4) * 4;
    const uint32_t d1 = (uint32_t)((r_ld + 64) * SAW + q_ld * 4) * 4;

    const int tl = lane >> 3, rw = lane & 7;
    const uint32_t aoff = (uint32_t)(((tl & 1) * 8 + rw) * SAW * 4 + (tl >> 1) * 16);
    const uint32_t boff = (uint32_t)(((tl >> 1) * 8 + rw) * SAW * 4 + (tl & 1) * 16);

    float acc[2][8][4];
#pragma unroll
    for (int mt = 0; mt < 2; mt++)
#pragma unroll
        for (int nt = 0; nt < 8; nt++)
#pragma unroll
            for (int r = 0; r < 4; r++) acc[mt][nt][r] = 0.f;

    const int nkt = K >> 5;

#define ISSUE1(KT, BUF)                                                         \
    do {                                                                        \
        uint32_t bs = sb + (BUF) * BUFSZ1;                                      \
        size_t ka = (size_t)(m0 + r_ld) * K + (KT) * 32 + q_ld * 8;             \
        size_t kb = (size_t)(n0 + r_ld) * K + (KT) * 32 + q_ld * 8;             \
        cp16(bs + d0, Ah + ka);                                                 \
        cp16(bs + d1, Ah + ka + (size_t)64 * K);                                \
        cp16(bs + OFF_AL1 + d0, Al + ka);                                       \
        cp16(bs + OFF_AL1 + d1, Al + ka + (size_t)64 * K);                      \
        cp16b(bs + OFF_B1 + d0, B + kb);                                        \
        cp16b(bs + OFF_B1 + d1, B + kb + (size_t)64 * K);                       \
        cp_commit();                                                            \
    } while (0)

    ISSUE1(0, 0);
    ISSUE1(1, 1);

    for (int kt = 0; kt < nkt; kt++) {
        if (kt + 1 < nkt)
            asm volatile("cp.async.wait_group 1;" ::: "memory");
        else
            asm volatile("cp.async.wait_group 0;" ::: "memory");
        __syncthreads();
        if (kt + 2 < nkt) ISSUE1(kt + 2, (kt + 2) % 3);

        uint32_t bs = sb + (uint32_t)(kt % 3) * BUFSZ1;
        uint32_t abase = bs + aoff + (uint32_t)(wm * 32) * SAW * 4;
        uint32_t bbase = bs + OFF_B1 + boff + (uint32_t)(wn * 64) * SAW * 4;
        gemm_ktile<4>(acc, abase, bbase, OFF_AL1);
    }

    gemm_epilogue<GELU, RES, OUTM, 4>(acc, m0, n0, wm, wn, g, c, bias, res,
                                      outf, outh, outl, N);
}

// ---------------- GEMM 128x96 (256 thr, 3-stage) -- for N=768 GEMMs -------------
#define OFF_AL9 10240u
#define OFF_B9  20480u
#define BUFSZ9  28160u
#define GSM9    (3 * 28160)

template <bool GELU, bool RES, int OUTM>
__global__ void __launch_bounds__(256, 2) gemm_mma96(
    const f16* __restrict__ Ah, const f16* __restrict__ Al,
    const f16* __restrict__ B,
    const float* __restrict__ bias, const float* __restrict__ res,
    float* __restrict__ outf, f16* __restrict__ outh, f16* __restrict__ outl,
    int M, int N, int K) {
    extern __shared__ char smem[];
    const uint32_t sb = smem_u32(smem);
    const int tid = threadIdx.x;
    const int lane = tid & 31, wid = tid >> 5;
    const int g = lane >> 2, c = lane & 3;
    const int wm = wid & 3, wn = wid >> 2;
    const int m0 = blockIdx.y * 128, n0 = blockIdx.x * 96;

    const int r_ld = tid >> 2;
    const int q_ld = tid & 3;
    const uint32_t d0 = (uint32_t)(r_ld * SAW + q_ld * 4) * 4;
    const uint32_t d1 = (uint32_t)((r_ld + 64) * SAW + q_ld * 4) * 4;
    const int rb1 = tid >> 2, qb1 = tid & 3;
    const int t2 = tid + 256;
    const int rb2 = t2 >> 2, qb2v = t2 & 3;
    const uint32_t db1 = (uint32_t)(rb1 * SAW + qb1 * 4) * 4;
    const uint32_t db2 = (uint32_t)(rb2 * SAW + qb2v * 4) * 4;
    const bool doB2 = (tid < 128);

    const int tl = lane >> 3, rw = lane & 7;
    const uint32_t aoff = (uint32_t)(((tl & 1) * 8 + rw) * SAW * 4 + (tl >> 1) * 16);
    const uint32_t boff = (uint32_t)(((tl >> 1) * 8 + rw) * SAW * 4 + (tl & 1) * 16);

    float acc[2][6][4];
#pragma unroll
    for (int mt = 0; mt < 2; mt++)
#pragma unroll
        for (int nt = 0; nt < 6; nt++)
#pragma unroll
            for (int r = 0; r < 4; r++) acc[mt][nt][r] = 0.f;

    const int nkt = K >> 5;

#define ISSUE9(KT, BUF)                                                         \
    do {                                                                        \
        uint32_t bs = sb + (BUF) * BUFSZ9;                                      \
        size_t ka = (size_t)(m0 + r_ld) * K + (KT) * 32 + q_ld * 8;             \
        cp16(bs + d0, Ah + ka);                                                 \
        cp16(bs + d1, Ah + ka + (size_t)64 * K);                                \
        cp16(bs + OFF_AL9 + d0, Al + ka);                                       \
        cp16(bs + OFF_AL9 + d1, Al + ka + (size_t)64 * K);                      \
        size_t kb = (size_t)(n0 + rb1) * K + (KT) * 32 + qb1 * 8;               \
        cp16b(bs + OFF_B9 + db1, B + kb);                                       \
        if (doB2) {                                                             \
            size_t kb2 = (size_t)(n0 + rb2) * K + (KT) * 32 + qb2v * 8;         \
            cp16b(bs + OFF_B9 + db2, B + kb2);                                  \
        }                                                                       \
        cp_commit();                                                            \
    } while (0)

    ISSUE9(0, 0);
    ISSUE9(1, 1);

    for (int kt = 0; kt < nkt; kt++) {
        if (kt + 1 < nkt)
            asm volatile("cp.async.wait_group 1;" ::: "memory");
        else
            asm volatile("cp.async.wait_group 0;" ::: "memory");
        __syncthreads();
        if (kt + 2 < nkt) ISSUE9(kt + 2, (kt + 2) % 3);

        uint32_t bs = sb + (uint32_t)(kt % 3) * BUFSZ9;
        uint32_t abase = bs + aoff + (uint32_t)(wm * 32) * SAW * 4;
        uint32_t bbase = bs + OFF_B9 + boff + (uint32_t)(wn * 48) * SAW * 4;
        gemm_ktile<3>(acc, abase, bbase, OFF_AL9);
    }

    gemm_epilogue<GELU, RES, OUTM, 3>(acc, m0, n0, wm, wn, g, c, bias, res,
                                      outf, outh, outl, N);
}

// ---------------- flash attention: 3-stage cp.async K/V, pipelined fragments ---
#define QSZ (128 * 72)
#define KVSTG (2 * 64 * 72)
#define ATTN_SMEM ((QSZ + 3 * KVSTG) * 2)   // 73728 B

__global__ void __launch_bounds__(256) attn16_kernel(const f16* __restrict__ qkv,
                                                     f16* __restrict__ yh,
                                                     f16* __restrict__ yl) {
    extern __shared__ f16 sh[];
    const uint32_t sQa = smem_u32(sh);

    const int qb = gridDim.x - 1 - blockIdx.x;   // longest CTAs first
    const int b = blockIdx.y / Hh, h = blockIdx.y % Hh;
    const int tid = threadIdx.x, lane = tid & 31, wid = tid >> 5;
    const int g = lane >> 2, c = lane & 3;
    const int tl = lane >> 3, rw = lane & 7;
    const f16* base = qkv + (size_t)b * Tt * (3 * Cc) + h * Dd;

    const uint32_t aoff = (uint32_t)(((tl & 1) * 8 + rw) * 72 + (tl >> 1) * 8) * 2;
    const uint32_t boff = (uint32_t)(((tl >> 1) * 8 + rw) * 72 + (tl & 1) * 8) * 2;

#pragma unroll
    for (int l = 0; l < 4; l++) {
        int ch = tid + l * 256;
        int r = ch >> 3, c8 = ch & 7;
        cp16(sQa + (uint32_t)(r * 72 + c8 * 8) * 2,
             base + (size_t)(qb * 128 + r) * (3 * Cc) + c8 * 8);
    }
    cp_commit();

    const int kbmax = 2 * qb + 1;

#define SKB(S) (sQa + (uint32_t)(QSZ + (S) * KVSTG) * 2)
#define SVB(S) (sQa + (uint32_t)(QSZ + (S) * KVSTG + 64 * 72) * 2)

#define ISSUEKV(KB, S)                                                          \
    do {                                                                        \
        uint32_t kk = SKB(S), vv = SVB(S);                                      \
        _Pragma("unroll")                                                       \
        for (int l = 0; l < 2; l++) {                                           \
            int ch = tid + l * 256;                                             \
            int r = ch >> 3, c8 = ch & 7;                                       \
            uint32_t so = (uint32_t)(r * 72 + c8 * 8) * 2;                      \
            const f16* gp = base + (size_t)((KB) * 64 + r) * (3 * Cc) + c8 * 8; \
            cp16(kk + so, gp + Cc);                                             \
            cp16(vv + so, gp + 2 * Cc);                                         \
        }                                                                       \
        cp_commit();                                                            \
    } while (0)

    ISSUEKV(0, 0);
    ISSUEKV(1, 1);

    asm volatile("cp.async.wait_group 2;" ::: "memory");  // Q done
    __syncthreads();

    uint32_t qf[4][4];
    {
        uint32_t qa = sQa + (uint32_t)(wid * 16) * 144 + aoff;
#pragma unroll
        for (int t = 0; t < 4; t++) ldsm4(qf[t], qa + t * 32);
    }

    float o[8][4];
#pragma unroll
    for (int j = 0; j < 8; j++)
#pragma unroll
        for (int r = 0; r < 4; r++) o[j][r] = 0.f;
    float mi0 = -1e30f, mi1 = -1e30f, li0 = 0.f, li1 = 0.f;
    const int row0 = qb * 128 + wid * 16 + g;
    const int row1 = row0 + 8;
    const int wqmax = qb * 128 + wid * 16 + 15;

    for (int kb = 0; kb <= kbmax; kb++) {
        if (kb + 1 <= kbmax)
            asm volatile("cp.async.wait_group 1;" ::: "memory");
        else
            asm volatile("cp.async.wait_group 0;" ::: "memory");
        __syncthreads();
        if (kb + 2 <= kbmax) ISSUEKV(kb + 2, (kb + 2) % 3);

        uint32_t sK = SKB(kb % 3), sV = SVB(kb % 3);

        if (kb * 64 <= wqmax) {
            // ---- S = Q K^T, K fragments pipelined one step ahead ----
            float s[8][4];
#pragma unroll
            for (int j = 0; j < 8; j++)
#pragma unroll
                for (int r = 0; r < 4; r++) s[j][r] = 0.f;
            {
                uint32_t kf[4];
                ldsm4(kf, sK + boff);   // jj=0, t=0
#pragma unroll
                for (int jj = 0; jj < 4; jj++) {
                    uint32_t kbse = sK + boff + (uint32_t)(jj * 16) * 144;
#pragma unroll
                    for (int t = 0; t < 4; t++) {
                        uint32_t kfn[4];
                        // prefetch next (t+1 within jj, else jj+1 t=0)
                        if (t + 1 < 4)
                            ldsm4(kfn, kbse + (t + 1) * 32);
                        else if (jj + 1 < 4)
                            ldsm4(kfn, sK + boff + (uint32_t)((jj + 1) * 16) * 144);
                        mma16(s[2 * jj], qf[t], kf[0], kf[1]);
                        mma16(s[2 * jj + 1], qf[t], kf[2], kf[3]);
                        if (t + 1 < 4 || jj + 1 < 4) {
                            kf[0] = kfn[0]; kf[1] = kfn[1];
                            kf[2] = kfn[2]; kf[3] = kfn[3];
                        }
                    }
                }
            }
            const bool doMask = (kb * 64 + 63) > (qb * 128 + wid * 16);
#pragma unroll
            for (int j = 0; j < 8; j++) {
                int col = kb * 64 + 8 * j + 2 * c;
                s[j][0] *= 0.125f; s[j][1] *= 0.125f;
                s[j][2] *= 0.125f; s[j][3] *= 0.125f;
                if (doMask) {
                    if (col > row0) s[j][0] = -1e30f;
                    if (col + 1 > row0) s[j][1] = -1e30f;
                    if (col > row1) s[j][2] = -1e30f;
                    if (col + 1 > row1) s[j][3] = -1e30f;
                }
            }
            float rm0 = -1e30f, rm1 = -1e30f;
#pragma unroll
            for (int j = 0; j < 8; j++) {
                rm0 = fmaxf(rm0, fmaxf(s[j][0], s[j][1]));
                rm1 = fmaxf(rm1, fmaxf(s[j][2], s[j][3]));
            }
            rm0 = fmaxf(rm0, __shfl_xor_sync(0xffffffffu, rm0, 1));
            rm0 = fmaxf(rm0, __shfl_xor_sync(0xffffffffu, rm0, 2));
            rm1 = fmaxf(rm1, __shfl_xor_sync(0xffffffffu, rm1, 1));
            rm1 = fmaxf(rm1, __shfl_xor_sync(0xffffffffu, rm1, 2));
            float mn0 = fmaxf(mi0, rm0), mn1 = fmaxf(mi1, rm1);
            float al0 = __expf(mi0 - mn0), al1 = __expf(mi1 - mn1);
            float rs0 = 0.f, rs1 = 0.f;
#pragma unroll
            for (int j = 0; j < 8; j++) {
                s[j][0] = __expf(s[j][0] - mn0);
                s[j][1] = __expf(s[j][1] - mn0);
                s[j][2] = __expf(s[j][2] - mn1);
                s[j][3] = __expf(s[j][3] - mn1);
                rs0 += s[j][0] + s[j][1];
                rs1 += s[j][2] + s[j][3];
            }
            rs0 += __shfl_xor_sync(0xffffffffu, rs0, 1);
            rs0 += __shfl_xor_sync(0xffffffffu, rs0, 2);
            rs1 += __shfl_xor_sync(0xffffffffu, rs1, 1);
            rs1 += __shfl_xor_sync(0xffffffffu, rs1, 2);
            li0 = li0 * al0 + rs0;
            li1 = li1 * al1 + rs1;
            mi0 = mn0; mi1 = mn1;
#pragma unroll
            for (int j = 0; j < 8; j++) {
                o[j][0] *= al0; o[j][1] *= al0;
                o[j][2] *= al1; o[j][3] *= al1;
            }
            uint32_t pa[4][4];
#pragma unroll
            for (int t = 0; t < 4; t++) {
                pa[t][0] = packh2(s[2 * t][0], s[2 * t][1]);
                pa[t][1] = packh2(s[2 * t][2], s[2 * t][3]);
                pa[t][2] = packh2(s[2 * t + 1][0], s[2 * t + 1][1]);
                pa[t][3] = packh2(s[2 * t + 1][2], s[2 * t + 1][3]);
            }
            // ---- O += P @ V, V fragments pipelined one step ahead ----
            {
                uint32_t vf[4];
                ldsm4t(vf, sV + aoff);   // jj=0, t=0
#pragma unroll
                for (int jj = 0; jj < 4; jj++) {
#pragma unroll
                    for (int t = 0; t < 4; t++) {
                        uint32_t vfn[4];
                        if (t + 1 < 4)
                            ldsm4t(vfn, sV + aoff + (uint32_t)((t + 1) * 16) * 144 + jj * 32);
                        else if (jj + 1 < 4)
                            ldsm4t(vfn, sV + aoff + (jj + 1) * 32);
                        mma16(o[2 * jj], pa[t], vf[0], vf[1]);
                        mma16(o[2 * jj + 1], pa[t], vf[2], vf[3]);
                        if (t + 1 < 4 || jj + 1 < 4) {
                            vf[0] = vfn[0]; vf[1] = vfn[1];
                            vf[2] = vfn[2]; vf[3] = vfn[3];
                        }
                    }
                }
            }
        }
    }

    float inv0 = 1.f / li0, inv1 = 1.f / li1;
    size_t rb0 = ((size_t)b * Tt + qb * 128 + wid * 16 + g) * Cc + h * Dd;
    size_t rb1 = rb0 + (size_t)8 * Cc;
#pragma unroll
    for (int j = 0; j < 8; j++) {
        int col = 8 * j + 2 * c;
        f16 h0, l0, h1, l1;
        split2(o[j][0] * inv0, h0, l0);
        split2(o[j][1] * inv0, h1, l1);
        __half2 hv; hv.x = h0; hv.y = h1;
        __half2 lv; lv.x = l0; lv.y = l1;
        *(__half2*)(yh + rb0 + col) = hv;
        *(__half2*)(yl + rb0 + col) = lv;
        split2(o[j][2] * inv1, h0, l0);
        split2(o[j][3] * inv1, h1, l1);
        hv.x = h0; hv.y = h1;
        lv.x = l0; lv.y = l1;
        *(__half2*)(yh + rb1 + col) = hv;
        *(__half2*)(yl + rb1 + col) = lv;
    }
}

// ---------------- final LN + head matvec --------------------------------------
__global__ void head_kernel(const float* __restrict__ x, const float* __restrict__ w,
                            const float* __restrict__ b, const float* __restrict__ wh,
                            float* __restrict__ out) {
    int row = blockIdx.x;
    int t = threadIdx.x;
    const float* xr = x + (size_t)row * Cc;
    float v[3];
    float s = 0.f, s2 = 0.f;
#pragma unroll
    for (int i = 0; i < 3; i++) { v[i] = xr[t + i * 256]; s += v[i]; s2 += v[i] * v[i]; }
#pragma unroll
    for (int m = 16; m; m >>= 1) {
        s  += __shfl_xor_sync(0xffffffffu, s, m);
        s2 += __shfl_xor_sync(0xffffffffu, s2, m);
    }
    __shared__ float rs[8], rs2[8], rd[8];
    if ((t & 31) == 0) { rs[t >> 5] = s; rs2[t >> 5] = s2; }
    __syncthreads();
    s = 0.f; s2 = 0.f;
#pragma unroll
    for (int i = 0; i < 8; i++) { s += rs[i]; s2 += rs2[i]; }
    float mu = s * (1.0f / Cc);
    float var = s2 * (1.0f / Cc) - mu * mu;
    float rstd = rsqrtf(var + 1e-5f);
    float dot = 0.f;
#pragma unroll
    for (int i = 0; i < 3; i++) {
        int c = t + i * 256;
        dot += ((v[i] - mu) * rstd * w[c] + b[c]) * wh[c];
    }
#pragma unroll
    for (int m = 16; m; m >>= 1) dot += __shfl_xor_sync(0xffffffffu, dot, m);
    if ((t & 31) == 0) rd[t >> 5] = dot;
    __syncthreads();
    if (t == 0) {
        float d = 0.f;
#pragma unroll
        for (int i = 0; i < 8; i++) d += rd[i];
        out[row] = d;
    }
}

// ---------------- host launch --------------------------------------------------
extern "C" void kernel_launch(void* const* d_in, const int* in_sizes, int n_in,
                              void* d_out, int out_size) {
    (void)in_sizes; (void)n_in; (void)out_size;
    const int*   idx   = (const int*)d_in[0];
    const float* wte   = (const float*)d_in[1];
    const float* wpe   = (const float*)d_in[2];
    const float* ln1w  = (const float*)d_in[3];
    const float* ln1b  = (const float*)d_in[4];
    const float* wqkv  = (const float*)d_in[5];
    const float* bqkv  = (const float*)d_in[6];
    const float* wao   = (const float*)d_in[7];
    const float* bao   = (const float*)d_in[8];
    const float* ln2w  = (const float*)d_in[9];
    const float* ln2b  = (const float*)d_in[10];
    const float* wfc   = (const float*)d_in[11];
    const float* bfc   = (const float*)d_in[12];
    const float* wfp   = (const float*)d_in[13];
    const float* bfp   = (const float*)d_in[14];
    const float* lnfw  = (const float*)d_in[15];
    const float* lnfb  = (const float*)d_in[16];
    const float* whead = (const float*)d_in[17];

    float* x;
    f16 *qkv16, *hh, *hl, *yh, *yl, *ffh, *ffl;
    f16 *wqkvT, *waoT, *wfcT, *wfpT;
    cudaGetSymbolAddress((void**)&x, g_x);
    cudaGetSymbolAddress((void**)&qkv16, g_qkv16);
    cudaGetSymbolAddress((void**)&hh, g_hh);
    cudaGetSymbolAddress((void**)&hl, g_hl);
    cudaGetSymbolAddress((void**)&yh, g_yh);
    cudaGetSymbolAddress((void**)&yl, g_yl);
    cudaGetSymbolAddress((void**)&ffh, g_ffh);
    cudaGetSymbolAddress((void**)&ffl, g_ffl);
    cudaGetSymbolAddress((void**)&wqkvT, g_wqkvT);
    cudaGetSymbolAddress((void**)&waoT, g_waoT);
    cudaGetSymbolAddress((void**)&wfcT, g_wfcT);
    cudaGetSymbolAddress((void**)&wfpT, g_wfpT);

    cudaFuncSetAttribute((const void*)attn16_kernel,
                         cudaFuncAttributeMaxDynamicSharedMemorySize, ATTN_SMEM);
    cudaFuncSetAttribute((const void*)gemm_mma<false, false, 1>,
                         cudaFuncAttributeMaxDynamicSharedMemorySize, GSM1);
    cudaFuncSetAttribute((const void*)gemm_mma<true, false, 2>,
                         cudaFuncAttributeMaxDynamicSharedMemorySize, GSM1);
    cudaFuncSetAttribute((const void*)gemm_mma96<false, true, 0>,
                         cudaFuncAttributeMaxDynamicSharedMemorySize, GSM9);

    wsplit_all<<<WS_ALL, 256>>>(wqkv, wao, wfc, wfp, wqkvT, waoT, wfcT, wfpT);

    embed_kernel<<<BT, 192>>>(idx, wte, wpe, x);

    for (int l = 0; l < Ll; l++) {
        ln_kernel<<<BT, 192>>>(x, ln1w + l * Cc, ln1b + l * Cc, hh, hl);
        gemm_mma<false, false, 1><<<dim3(18, 32), 256, GSM1>>>(
            hh, hl, wqkvT + (size_t)l * 3 * Cc * Cc, bqkv + l * 3 * Cc,
            nullptr, nullptr, qkv16, nullptr, BT, 3 * Cc, Cc);
        attn16_kernel<<<dim3(Tt / 128, Bq * Hh), 256, ATTN_SMEM>>>(qkv16, yh, yl);
        gemm_mma96<false, true, 0><<<dim3(8, 32), 256, GSM9>>>(
            yh, yl, waoT + (size_t)l * Cc * Cc, bao + l * Cc,
            x, x, nullptr, nullptr, BT, Cc, Cc);
        ln_kernel<<<BT, 192>>>(x, ln2w + l * Cc, ln2b + l * Cc, hh, hl);
        gemm_mma<true, false, 2><<<dim3(24, 32), 256, GSM1>>>(
            hh, hl, wfcT + (size_t)l * 4 * Cc * Cc, bfc + l * 4 * Cc,
            nullptr, nullptr, ffh, ffl, BT, 4 * Cc, Cc);
        gemm_mma96<false, true, 0><<<dim3(8, 32), 256, GSM9>>>(
            ffh, ffl, wfpT + (size_t)l * Cc * 4 * Cc, bfp + l * Cc,
            x, x, nullptr, nullptr, BT, Cc, 4 * Cc);
    }

    head_kernel<<<BT, 256>>>(x, lnfw, lnfb, whead, (float*)d_out);
}

// round 16
// speedup vs baseline: 1.0028x; 1.0028x over previous
#include <cuda_runtime.h>
#include <cuda_fp16.h>
#include <math.h>
#include <stdint.h>

#define Bq 4
#define Tt 1024
#define Cc 768
#define Hh 12
#define Dd 64
#define Ll 12
#define BT 4096

typedef __half f16;

// ---------------- scratch (device globals) ------------------------------------
__device__ __align__(16) float g_x[BT * Cc];
__device__ __align__(16) f16 g_qkv16[BT * 3 * Cc];

__device__ __align__(16) f16 g_hh[BT * Cc];
__device__ __align__(16) f16 g_hl[BT * Cc];
__device__ __align__(16) f16 g_yh[BT * Cc];
__device__ __align__(16) f16 g_yl[BT * Cc];
__device__ __align__(16) f16 g_ffh[BT * 4 * Cc];
__device__ __align__(16) f16 g_ffl[BT * 4 * Cc];

__device__ __align__(16) f16 g_wqkvT[Ll * 3 * Cc * Cc];
__device__ __align__(16) f16 g_waoT[Ll * Cc * Cc];
__device__ __align__(16) f16 g_wfcT[Ll * 4 * Cc * Cc];
__device__ __align__(16) f16 g_wfpT[Ll * Cc * 4 * Cc];

// ---------------- helpers -----------------------------------------------------
__device__ __forceinline__ uint32_t smem_u32(const void* p) {
    uint32_t a;
    asm("{ .reg .u64 t; cvta.to.shared.u64 t, %1; cvt.u32.u64 %0, t; }"
        : "=r"(a) : "l"(p));
    return a;
}
__device__ __forceinline__ void ldsm4(uint32_t* r, uint32_t addr) {
    asm volatile("ldmatrix.sync.aligned.m8n8.x4.shared.b16 {%0,%1,%2,%3}, [%4];"
                 : "=r"(r[0]), "=r"(r[1]), "=r"(r[2]), "=r"(r[3]) : "r"(addr));
}
__device__ __forceinline__ void ldsm4t(uint32_t* r, uint32_t addr) {
    asm volatile("ldmatrix.sync.aligned.m8n8.x4.trans.shared.b16 {%0,%1,%2,%3}, [%4];"
                 : "=r"(r[0]), "=r"(r[1]), "=r"(r[2]), "=r"(r[3]) : "r"(addr));
}
__device__ __forceinline__ void cp16(uint32_t dst, const void* src) {
    asm volatile("cp.async.ca.shared.global [%0], [%1], 16;"
                 :: "r"(dst), "l"(src) : "memory");
}
__device__ __forceinline__ void cp16b(uint32_t dst, const void* src) {
    asm volatile("cp.async.ca.shared.global.L2::256B [%0], [%1], 16;"
                 :: "r"(dst), "l"(src) : "memory");
}
__device__ __forceinline__ void cp_commit() {
    asm volatile("cp.async.commit_group;" ::: "memory");
}
__device__ __forceinline__ void mma16(float* c, const uint32_t* a,
                                      uint32_t b0, uint32_t b1) {
    asm volatile(
        "mma.sync.aligned.m16n8k16.row.col.f32.f16.f16.f32 "
        "{%0,%1,%2,%3}, {%4,%5,%6,%7}, {%8,%9}, {%0,%1,%2,%3};"
        : "+f"(c[0]), "+f"(c[1]), "+f"(c[2]), "+f"(c[3])
        : "r"(a[0]), "r"(a[1]), "r"(a[2]), "r"(a[3]), "r"(b0), "r"(b1));
}
__device__ __forceinline__ void split2(float f, f16& h, f16& l) {
    h = __float2half_rn(f);
    l = __float2half_rn(f - __half2float(h));
}
__device__ __forceinline__ float gelu_f(float x) {
    float x3 = x * x * x;
    return 0.5f * x * (1.f + tanhf(0.7978845608028654f * (x + 0.044715f * x3)));
}
__device__ __forceinline__ uint32_t packh2(float a, float b) {
    __half2 h = __floats2half2_rn(a, b);
    return *(uint32_t*)&h;
}

// ---------------- weight transpose to fp16 (all 4 weights, one launch) ---------
#define WS_QKV 20736
#define WS_AO  (WS_QKV + 6912)
#define WS_FC  (WS_AO + 27648)
#define WS_ALL (WS_FC + 27648)

__global__ void wsplit_all(const float* __restrict__ wqkv, const float* __restrict__ wao,
                           const float* __restrict__ wfc, const float* __restrict__ wfp,
                           f16* __restrict__ tqkv, f16* __restrict__ tao,
                           f16* __restrict__ tfc, f16* __restrict__ tfp) {
    __shared__ float t[32][33];
    int bid = blockIdx.x;
    const float* W;
    f16* T;
    int K, N, nx, base;
    if (bid < WS_QKV)     { W = wqkv; T = tqkv; K = Cc;     N = 3 * Cc; nx = 72; base = bid; }
    else if (bid < WS_AO) { W = wao;  T = tao;  K = Cc;     N = Cc;     nx = 24; base = bid - WS_QKV; }
    else if (bid < WS_FC) { W = wfc;  T = tfc;  K = Cc;     N = 4 * Cc; nx = 96; base = bid - WS_AO; }
    else                  { W = wfp;  T = tfp;  K = 4 * Cc; N = Cc;     nx = 24; base = bid - WS_FC; }
    int per_layer = nx * (K >> 5);
    int layer = base / per_layer;
    int rem = base - layer * per_layer;
    int bx = rem % nx, by = rem / nx;
    size_t loff = (size_t)layer * K * N;
    const float* Wl = W + loff;
    f16* Tl = T + loff;
    int n0 = bx * 32, k0 = by * 32;
    int tx = threadIdx.x & 31, ty = threadIdx.x >> 5;
#pragma unroll
    for (int j = 0; j < 4; j++)
        t[ty + 8 * j][tx] = Wl[(size_t)(k0 + ty + 8 * j) * N + n0 + tx];
    __syncthreads();
#pragma unroll
    for (int j = 0; j < 4; j++) {
        int nr = ty + 8 * j;
        Tl[(size_t)(n0 + nr) * K + k0 + tx] = __float2half_rn(t[tx][nr]);
    }
}

// ---------------- embedding ---------------------------------------------------
__global__ void embed_kernel(const int* __restrict__ idx, const float* __restrict__ wte,
                             const float* __restrict__ wpe, float* __restrict__ x) {
    int row = blockIdx.x;
    int tok = idx[row];
    int t = row & (Tt - 1);
    int c = threadIdx.x * 4;
    float4 a = *(const float4*)(wte + (size_t)tok * Cc + c);
    float4 p = *(const float4*)(wpe + (size_t)t * Cc + c);
    a.x += p.x; a.y += p.y; a.z += p.z; a.w += p.w;
    *(float4*)(x + (size_t)row * Cc + c) = a;
}

// ---------------- layernorm (fp32 in, hi/lo fp16 out) -- 192 thr, float4 -------
__global__ void ln_kernel(const float* __restrict__ in, const float* __restrict__ w,
                          const float* __restrict__ b, f16* __restrict__ oh,
                          f16* __restrict__ ol) {
    int row = blockIdx.x;
    int t = threadIdx.x;   // 0..191
    float4 v = *(const float4*)(in + (size_t)row * Cc + t * 4);
    float s = v.x + v.y + v.z + v.w;
    float s2 = v.x * v.x + v.y * v.y + v.z * v.z + v.w * v.w;
#pragma unroll
    for (int m = 16; m; m >>= 1) {
        s  += __shfl_xor_sync(0xffffffffu, s, m);
        s2 += __shfl_xor_sync(0xffffffffu, s2, m);
    }
    __shared__ float rs[6], rs2[6];
    if ((t & 31) == 0) { rs[t >> 5] = s; rs2[t >> 5] = s2; }
    __syncthreads();
    s = 0.f; s2 = 0.f;
#pragma unroll
    for (int i = 0; i < 6; i++) { s += rs[i]; s2 += rs2[i]; }
    float mu = s * (1.0f / Cc);
    float var = s2 * (1.0f / Cc) - mu * mu;
    float rstd = rsqrtf(var + 1e-5f);
    float4 wv = *(const float4*)(w + t * 4);
    float4 bv = *(const float4*)(b + t * 4);
    float o0 = (v.x - mu) * rstd * wv.x + bv.x;
    float o1 = (v.y - mu) * rstd * wv.y + bv.y;
    float o2 = (v.z - mu) * rstd * wv.z + bv.z;
    float o3 = (v.w - mu) * rstd * wv.w + bv.w;
    f16 h0, l0, h1, l1, h2, l2, h3, l3;
    split2(o0, h0, l0); split2(o1, h1, l1); split2(o2, h2, l2); split2(o3, h3, l3);
    __half2 hA, hB, lA, lB;
    hA.x = h0; hA.y = h1; hB.x = h2; hB.y = h3;
    lA.x = l0; lA.y = l1; lB.x = l2; lB.y = l3;
    size_t off = (size_t)row * Cc + t * 4;
    *(__half2*)(oh + off) = hA;
    *(__half2*)(oh + off + 2) = hB;
    *(__half2*)(ol + off) = lA;
    *(__half2*)(ol + off + 2) = lB;
}

// ---------------- shared GEMM pieces -------------------------------------------
#define SAW 20

template <bool GELU, bool RES, int OUTM, int NJ>
__device__ __forceinline__ void gemm_epilogue(
    float acc[2][2 * NJ][4], int m0, int n0, int wm, int wn, int g, int c,
    const float* __restrict__ bias, const float* __restrict__ res,
    float* __restrict__ outf, f16* __restrict__ outh, f16* __restrict__ outl, int N) {
#pragma unroll
    for (int mt = 0; mt < 2; mt++) {
        int rbase = m0 + wm * 32 + mt * 16 + g;
#pragma unroll
        for (int nt = 0; nt < 2 * NJ; nt++) {
            int col = n0 + wn * (NJ * 16) + nt * 8 + 2 * c;
            float b0v = bias[col], b1v = bias[col + 1];
#pragma unroll
            for (int rr = 0; rr < 2; rr++) {
                int r = rbase + rr * 8;
                float v0 = acc[mt][nt][rr * 2 + 0] + b0v;
                float v1 = acc[mt][nt][rr * 2 + 1] + b1v;
                if (GELU) { v0 = gelu_f(v0); v1 = gelu_f(v1); }
                if (RES) {
                    float2 rv = *(const float2*)(res + (size_t)r * N + col);
                    v0 += rv.x;
                    v1 += rv.y;
                }
                if (OUTM == 0) {
                    float2 ov; ov.x = v0; ov.y = v1;
                    *(float2*)(outf + (size_t)r * N + col) = ov;
                } else if (OUTM == 1) {
                    uint32_t hv = packh2(v0, v1);
                    *(uint32_t*)(outh + (size_t)r * N + col) = hv;
                } else {
                    f16 h0, l0, h1, l1;
                    split2(v0, h0, l0);
                    split2(v1, h1, l1);
                    __half2 hv; hv.x = h0; hv.y = h1;
                    __half2 lv; lv.x = l0; lv.y = l1;
                    *(__half2*)(outh + (size_t)r * N + col) = hv;
                    *(__half2*)(outl + (size_t)r * N + col) = lv;
                }
            }
        }
    }
}

// one k-tile; B-fragments pipelined one jj ahead (R14-proven) AND MMAs batched
// ah-group then al-group: per-accumulator order unchanged (ah before al) ->
// bit-identical numerics, but RAW distance on each accumulator goes 1 -> 4.
template <int NJ>
__device__ __forceinline__ void gemm_ktile(
    float acc[2][2 * NJ][4], uint32_t abase, uint32_t bbase, uint32_t offAL) {
#pragma unroll
    for (int ks = 0; ks < 2; ks++) {
        uint32_t ah[2][4], al[2][4];
#pragma unroll
        for (int mt = 0; mt < 2; mt++) {
            uint32_t ar = abase + (uint32_t)(mt * 16) * SAW * 4 + ks * 32;
            ldsm4(ah[mt], ar);
            ldsm4(al[mt], ar + offAL);
        }
        uint32_t bf[4];
        ldsm4(bf, bbase + ks * 32);
#pragma unroll
        for (int jj = 0; jj < NJ; jj++) {
            uint32_t bfn[4];
            if (jj + 1 < NJ)
                ldsm4(bfn, bbase + (uint32_t)((jj + 1) * 16) * SAW * 4 + ks * 32);
            // hi-group: 4 independent accumulators
            mma16(acc[0][2 * jj], ah[0], bf[0], bf[1]);
            mma16(acc[1][2 * jj], ah[1], bf[0], bf[1]);
            mma16(acc[0][2 * jj + 1], ah[0], bf[2], bf[3]);
            mma16(acc[1][2 * jj + 1], ah[1], bf[2], bf[3]);
            // lo-group: same accumulators, RAW distance 4
            mma16(acc[0][2 * jj], al[0], bf[0], bf[1]);
            mma16(acc[1][2 * jj], al[1], bf[0], bf[1]);
            mma16(acc[0][2 * jj + 1], al[0], bf[2], bf[3]);
            mma16(acc[1][2 * jj + 1], al[1], bf[2], bf[3]);
            if (jj + 1 < NJ) {
                bf[0] = bfn[0]; bf[1] = bfn[1]; bf[2] = bfn[2]; bf[3] = bfn[3];
            }
        }
    }
}

// ---------------- GEMM 128x128 (256 thr, 3-stage) ------------------------------
#define OFF_AL1 10240u
#define OFF_B1  20480u
#define BUFSZ1  30720u
#define GSM1    (3 * 30720)

template <bool GELU, bool RES, int OUTM>
__global__ void __launch_bounds__(256, 2) gemm_mma(
    const f16* __restrict__ Ah, const f16* __restrict__ Al,
    const f16* __restrict__ B,
    const float* __restrict__ bias, const float* __restrict__ res,
    float* __restrict__ outf, f16* __restrict__ outh, f16* __restrict__ outl,
    int M, int N, int K) {
    extern __shared__ char smem[];
    const uint32_t sb = smem_u32(smem);
    const int tid = threadIdx.x;
    const int lane = tid & 31, wid = tid >> 5;
    const int g = lane >> 2, c = lane & 3;
    const int wm = wid & 3, wn = wid >> 2;
    const int m0 = blockIdx.y * 128, n0 = blockIdx.x * 128;

    const int r_ld = tid >> 2;
    const int q_ld = tid & 3;
    const uint32_t d0 = (uint32_t)(r_ld * SAW + q_ld * 4) * 4;
    const uint32_t d1 = (uint32_t)((r_ld + 64) * SAW + q_ld * 4) * 4;

    const int tl = lane >> 3, rw = lane & 7;
    const uint32_t aoff = (uint32_t)(((tl & 1) * 8 + rw) * SAW * 4 + (tl >> 1) * 16);
    const uint32_t boff = (uint32_t)(((tl >> 1) * 8 + rw) * SAW * 4 + (tl & 1) * 16);

    float acc[2][8][4];
#pragma unroll
    for (int mt = 0; mt < 2; mt++)
#pragma unroll
        for (int nt = 0; nt < 8; nt++)
#pragma unroll
            for (int r = 0; r < 4; r++) acc[mt][nt][r] = 0.f;

    const int nkt = K >> 5;

#define ISSUE1(KT, BUF)                                                         \
    do {                                                                        \
        uint32_t bs = sb + (BUF) * BUFSZ1;                                      \
        size_t ka = (size_t)(m0 + r_ld) * K + (KT) * 32 + q_ld * 8;             \
        size_t kb = (size_t)(n0 + r_ld) * K + (KT) * 32 + q_ld * 8;             \
        cp16(bs + d0, Ah + ka);                                                 \
        cp16(bs + d1, Ah + ka + (size_t)64 * K);                                \
        cp16(bs + OFF_AL1 + d0, Al + ka);                                       \
        cp16(bs + OFF_AL1 + d1, Al + ka + (size_t)64 * K);                      \
        cp16b(bs + OFF_B1 + d0, B + kb);                                        \
        cp16b(bs + OFF_B1 + d1, B + kb + (size_t)64 * K);                       \
        cp_commit();                                                            \
    } while (0)

    ISSUE1(0, 0);
    ISSUE1(1, 1);

    for (int kt = 0; kt < nkt; kt++) {
        if (kt + 1 < nkt)
            asm volatile("cp.async.wait_group 1;" ::: "memory");
        else
            asm volatile("cp.async.wait_group 0;" ::: "memory");
        __syncthreads();
        if (kt + 2 < nkt) ISSUE1(kt + 2, (kt + 2) % 3);

        uint32_t bs = sb + (uint32_t)(kt % 3) * BUFSZ1;
        uint32_t abase = bs + aoff + (uint32_t)(wm * 32) * SAW * 4;
        uint32_t bbase = bs + OFF_B1 + boff + (uint32_t)(wn * 64) * SAW * 4;
        gemm_ktile<4>(acc, abase, bbase, OFF_AL1);
    }

    gemm_epilogue<GELU, RES, OUTM, 4>(acc, m0, n0, wm, wn, g, c, bias, res,
                                      outf, outh, outl, N);
}

// ---------------- GEMM 128x96 (256 thr, 3-stage) -- for N=768 GEMMs -------------
#define OFF_AL9 10240u
#define OFF_B9  20480u
#define BUFSZ9  28160u
#define GSM9    (3 * 28160)

template <bool GELU, bool RES, int OUTM>
__global__ void __launch_bounds__(256, 2) gemm_mma96(
    const f16* __restrict__ Ah, const f16* __restrict__ Al,
    const f16* __restrict__ B,
    const float* __restrict__ bias, const float* __restrict__ res,
    float* __restrict__ outf, f16* __restrict__ outh, f16* __restrict__ outl,
    int M, int N, int K) {
    extern __shared__ char smem[];
    const uint32_t sb = smem_u32(smem);
    const int tid = threadIdx.x;
    const int lane = tid & 31, wid = tid >> 5;
    const int g = lane >> 2, c = lane & 3;
    const int wm = wid & 3, wn = wid >> 2;
    const int m0 = blockIdx.y * 128, n0 = blockIdx.x * 96;

    const int r_ld = tid >> 2;
    const int q_ld = tid & 3;
    const uint32_t d0 = (uint32_t)(r_ld * SAW + q_ld * 4) * 4;
    const uint32_t d1 = (uint32_t)((r_ld + 64) * SAW + q_ld * 4) * 4;
    const int rb1 = tid >> 2, qb1 = tid & 3;
    const int t2 = tid + 256;
    const int rb2 = t2 >> 2, qb2v = t2 & 3;
    const uint32_t db1 = (uint32_t)(rb1 * SAW + qb1 * 4) * 4;
    const uint32_t db2 = (uint32_t)(rb2 * SAW + qb2v * 4) * 4;
    const bool doB2 = (tid < 128);

    const int tl = lane >> 3, rw = lane & 7;
    const uint32_t aoff = (uint32_t)(((tl & 1) * 8 + rw) * SAW * 4 + (tl >> 1) * 16);
    const uint32_t boff = (uint32_t)(((tl >> 1) * 8 + rw) * SAW * 4 + (tl & 1) * 16);

    float acc[2][6][4];
#pragma unroll
    for (int mt = 0; mt < 2; mt++)
#pragma unroll
        for (int nt = 0; nt < 6; nt++)
#pragma unroll
            for (int r = 0; r < 4; r++) acc[mt][nt][r] = 0.f;

    const int nkt = K >> 5;

#define ISSUE9(KT, BUF)                                                         \
    do {                                                                        \
        uint32_t bs = sb + (BUF) * BUFSZ9;                                      \
        size_t ka = (size_t)(m0 + r_ld) * K + (KT) * 32 + q_ld * 8;             \
        cp16(bs + d0, Ah + ka);                                                 \
        cp16(bs + d1, Ah + ka + (size_t)64 * K);                                \
        cp16(bs + OFF_AL9 + d0, Al + ka);                                       \
        cp16(bs + OFF_AL9 + d1, Al + ka + (size_t)64 * K);                      \
        size_t kb = (size_t)(n0 + rb1) * K + (KT) * 32 + qb1 * 8;               \
        cp16b(bs + OFF_B9 + db1, B + kb);                                       \
        if (doB2) {                                                             \
            size_t kb2 = (size_t)(n0 + rb2) * K + (KT) * 32 + qb2v * 8;         \
            cp16b(bs + OFF_B9 + db2, B + kb2);                                  \
        }                                                                       \
        cp_commit();                                                            \
    } while (0)

    ISSUE9(0, 0);
    ISSUE9(1, 1);

    for (int kt = 0; kt < nkt; kt++) {
        if (kt + 1 < nkt)
            asm volatile("cp.async.wait_group 1;" ::: "memory");
        else
            asm volatile("cp.async.wait_group 0;" ::: "memory");
        __syncthreads();
        if (kt + 2 < nkt) ISSUE9(kt + 2, (kt + 2) % 3);

        uint32_t bs = sb + (uint32_t)(kt % 3) * BUFSZ9;
        uint32_t abase = bs + aoff + (uint32_t)(wm * 32) * SAW * 4;
        uint32_t bbase = bs + OFF_B9 + boff + (uint32_t)(wn * 48) * SAW * 4;
        gemm_ktile<3>(acc, abase, bbase, OFF_AL9);
    }

    gemm_epilogue<GELU, RES, OUTM, 3>(acc, m0, n0, wm, wn, g, c, bias, res,
                                      outf, outh, outl, N);
}

// ---------------- flash attention: 3-stage cp.async K/V, pipelined fragments ---
#define QSZ (128 * 72)
#define KVSTG (2 * 64 * 72)
#define ATTN_SMEM ((QSZ + 3 * KVSTG) * 2)   // 73728 B

__global__ void __launch_bounds__(256) attn16_kernel(const f16* __restrict__ qkv,
                                                     f16* __restrict__ yh,
                                                     f16* __restrict__ yl) {
    extern __shared__ f16 sh[];
    const uint32_t sQa = smem_u32(sh);

    const int qb = gridDim.x - 1 - blockIdx.x;   // longest CTAs first
    const int b = blockIdx.y / Hh, h = blockIdx.y % Hh;
    const int tid = threadIdx.x, lane = tid & 31, wid = tid >> 5;
    const int g = lane >> 2, c = lane & 3;
    const int tl = lane >> 3, rw = lane & 7;
    const f16* base = qkv + (size_t)b * Tt * (3 * Cc) + h * Dd;

    const uint32_t aoff = (uint32_t)(((tl & 1) * 8 + rw) * 72 + (tl >> 1) * 8) * 2;
    const uint32_t boff = (uint32_t)(((tl >> 1) * 8 + rw) * 72 + (tl & 1) * 8) * 2;

#pragma unroll
    for (int l = 0; l < 4; l++) {
        int ch = tid + l * 256;
        int r = ch >> 3, c8 = ch & 7;
        cp16(sQa + (uint32_t)(r * 72 + c8 * 8) * 2,
             base + (size_t)(qb * 128 + r) * (3 * Cc) + c8 * 8);
    }
    cp_commit();

    const int kbmax = 2 * qb + 1;

#define SKB(S) (sQa + (uint32_t)(QSZ + (S) * KVSTG) * 2)
#define SVB(S) (sQa + (uint32_t)(QSZ + (S) * KVSTG + 64 * 72) * 2)

#define ISSUEKV(KB, S)                                                          \
    do {                                                                        \
        uint32_t kk = SKB(S), vv = SVB(S);                                      \
        _Pragma("unroll")                                                       \
        for (int l = 0; l < 2; l++) {                                           \
            int ch = tid + l * 256;                                             \
            int r = ch >> 3, c8 = ch & 7;                                       \
            uint32_t so = (uint32_t)(r * 72 + c8 * 8) * 2;                      \
            const f16* gp = base + (size_t)((KB) * 64 + r) * (3 * Cc) + c8 * 8; \
            cp16(kk + so, gp + Cc);                                             \
            cp16(vv + so, gp + 2 * Cc);                                         \
        }                                                                       \
        cp_commit();                                                            \
    } while (0)

    ISSUEKV(0, 0);
    ISSUEKV(1, 1);

    asm volatile("cp.async.wait_group 2;" ::: "memory");  // Q done
    __syncthreads();

    uint32_t qf[4][4];
    {
        uint32_t qa = sQa + (uint32_t)(wid * 16) * 144 + aoff;
#pragma unroll
        for (int t = 0; t < 4; t++) ldsm4(qf[t], qa + t * 32);
    }

    float o[8][4];
#pragma unroll
    for (int j = 0; j < 8; j++)
#pragma unroll
        for (int r = 0; r < 4; r++) o[j][r] = 0.f;
    float mi0 = -1e30f, mi1 = -1e30f, li0 = 0.f, li1 = 0.f;
    const int row0 = qb * 128 + wid * 16 + g;
    const int row1 = row0 + 8;
    const int wqmax = qb * 128 + wid * 16 + 15;

    for (int kb = 0; kb <= kbmax; kb++) {
        if (kb + 1 <= kbmax)
            asm volatile("cp.async.wait_group 1;" ::: "memory");
        else
            asm volatile("cp.async.wait_group 0;" ::: "memory");
        __syncthreads();
        if (kb + 2 <= kbmax) ISSUEKV(kb + 2, (kb + 2) % 3);

        uint32_t sK = SKB(kb % 3), sV = SVB(kb % 3);

        if (kb * 64 <= wqmax) {
            // ---- S = Q K^T, K fragments pipelined one step ahead ----
            float s[8][4];
#pragma unroll
            for (int j = 0; j < 8; j++)
#pragma unroll
                for (int r = 0; r < 4; r++) s[j][r] = 0.f;
            {
                uint32_t kf[4];
                ldsm4(kf, sK + boff);   // jj=0, t=0
#pragma unroll
                for (int jj = 0; jj < 4; jj++) {
                    uint32_t kbse = sK + boff + (uint32_t)(jj * 16) * 144;
#pragma unroll
                    for (int t = 0; t < 4; t++) {
                        uint32_t kfn[4];
                        if (t + 1 < 4)
                            ldsm4(kfn, kbse + (t + 1) * 32);
                        else if (jj + 1 < 4)
                            ldsm4(kfn, sK + boff + (uint32_t)((jj + 1) * 16) * 144);
                        mma16(s[2 * jj], qf[t], kf[0], kf[1]);
                        mma16(s[2 * jj + 1], qf[t], kf[2], kf[3]);
                        if (t + 1 < 4 || jj + 1 < 4) {
                            kf[0] = kfn[0]; kf[1] = kfn[1];
                            kf[2] = kfn[2]; kf[3] = kfn[3];
                        }
                    }
                }
            }
            const bool doMask = (kb * 64 + 63) > (qb * 128 + wid * 16);
#pragma unroll
            for (int j = 0; j < 8; j++) {
                int col = kb * 64 + 8 * j + 2 * c;
                s[j][0] *= 0.125f; s[j][1] *= 0.125f;
                s[j][2] *= 0.125f; s[j][3] *= 0.125f;
                if (doMask) {
                    if (col > row0) s[j][0] = -1e30f;
                    if (col + 1 > row0) s[j][1] = -1e30f;
                    if (col > row1) s[j][2] = -1e30f;
                    if (col + 1 > row1) s[j][3] = -1e30f;
                }
            }
            float rm0 = -1e30f, rm1 = -1e30f;
#pragma unroll
            for (int j = 0; j < 8; j++) {
                rm0 = fmaxf(rm0, fmaxf(s[j][0], s[j][1]));
                rm1 = fmaxf(rm1, fmaxf(s[j][2], s[j][3]));
            }
            rm0 = fmaxf(rm0, __shfl_xor_sync(0xffffffffu, rm0, 1));
            rm0 = fmaxf(rm0, __shfl_xor_sync(0xffffffffu, rm0, 2));
            rm1 = fmaxf(rm1, __shfl_xor_sync(0xffffffffu, rm1, 1));
            rm1 = fmaxf(rm1, __shfl_xor_sync(0xffffffffu, rm1, 2));
            float mn0 = fmaxf(mi0, rm0), mn1 = fmaxf(mi1, rm1);
            float al0 = __expf(mi0 - mn0), al1 = __expf(mi1 - mn1);
            float rs0 = 0.f, rs1 = 0.f;
#pragma unroll
            for (int j = 0; j < 8; j++) {
                s[j][0] = __expf(s[j][0] - mn0);
                s[j][1] = __expf(s[j][1] - mn0);
                s[j][2] = __expf(s[j][2] - mn1);
                s[j][3] = __expf(s[j][3] - mn1);
                rs0 += s[j][0] + s[j][1];
                rs1 += s[j][2] + s[j][3];
            }
            rs0 += __shfl_xor_sync(0xffffffffu, rs0, 1);
            rs0 += __shfl_xor_sync(0xffffffffu, rs0, 2);
            rs1 += __shfl_xor_sync(0xffffffffu, rs1, 1);
            rs1 += __shfl_xor_sync(0xffffffffu, rs1, 2);
            li0 = li0 * al0 + rs0;
            li1 = li1 * al1 + rs1;
            mi0 = mn0; mi1 = mn1;
#pragma unroll
            for (int j = 0; j < 8; j++) {
                o[j][0] *= al0; o[j][1] *= al0;
                o[j][2] *= al1; o[j][3] *= al1;
            }
            uint32_t pa[4][4];
#pragma unroll
            for (int t = 0; t < 4; t++) {
                pa[t][0] = packh2(s[2 * t][0], s[2 * t][1]);
                pa[t][1] = packh2(s[2 * t][2], s[2 * t][3]);
                pa[t][2] = packh2(s[2 * t + 1][0], s[2 * t + 1][1]);
                pa[t][3] = packh2(s[2 * t + 1][2], s[2 * t + 1][3]);
            }
            // ---- O += P @ V, V fragments pipelined one step ahead ----
            {
                uint32_t vf[4];
                ldsm4t(vf, sV + aoff);   // jj=0, t=0
#pragma unroll
                for (int jj = 0; jj < 4; jj++) {
#pragma unroll
                    for (int t = 0; t < 4; t++) {
                        uint32_t vfn[4];
                        if (t + 1 < 4)
                            ldsm4t(vfn, sV + aoff + (uint32_t)((t + 1) * 16) * 144 + jj * 32);
                        else if (jj + 1 < 4)
                            ldsm4t(vfn, sV + aoff + (jj + 1) * 32);
                        mma16(o[2 * jj], pa[t], vf[0], vf[1]);
                        mma16(o[2 * jj + 1], pa[t], vf[2], vf[3]);
                        if (t + 1 < 4 || jj + 1 < 4) {
                            vf[0] = vfn[0]; vf[1] = vfn[1];
                            vf[2] = vfn[2]; vf[3] = vfn[3];
                        }
                    }
                }
            }
        }
    }

    float inv0 = 1.f / li0, inv1 = 1.f / li1;
    size_t rb0 = ((size_t)b * Tt + qb * 128 + wid * 16 + g) * Cc + h * Dd;
    size_t rb1 = rb0 + (size_t)8 * Cc;
#pragma unroll
    for (int j = 0; j < 8; j++) {
        int col = 8 * j + 2 * c;
        f16 h0, l0, h1, l1;
        split2(o[j][0] * inv0, h0, l0);
        split2(o[j][1] * inv0, h1, l1);
        __half2 hv; hv.x = h0; hv.y = h1;
        __half2 lv; lv.x = l0; lv.y = l1;
        *(__half2*)(yh + rb0 + col) = hv;
        *(__half2*)(yl + rb0 + col) = lv;
        split2(o[j][2] * inv1, h0, l0);
        split2(o[j][3] * inv1, h1, l1);
        hv.x = h0; hv.y = h1;
        lv.x = l0; lv.y = l1;
        *(__half2*)(yh + rb1 + col) = hv;
        *(__half2*)(yl + rb1 + col) = lv;
    }
}

// ---------------- final LN + head matvec --------------------------------------
__global__ void head_kernel(const float* __restrict__ x, const float* __restrict__ w,
                            const float* __restrict__ b, const float* __restrict__ wh,
                            float* __restrict__ out) {
    int row = blockIdx.x;
    int t = threadIdx.x;
    const float* xr = x + (size_t)row * Cc;
    float v[3];
    float s = 0.f, s2 = 0.f;
#pragma unroll
    for (int i = 0; i < 3; i++) { v[i] = xr[t + i * 256]; s += v[i]; s2 += v[i] * v[i]; }
#pragma unroll
    for (int m = 16; m; m >>= 1) {
        s  += __shfl_xor_sync(0xffffffffu, s, m);
        s2 += __shfl_xor_sync(0xffffffffu, s2, m);
    }
    __shared__ float rs[8], rs2[8], rd[8];
    if ((t & 31) == 0) { rs[t >> 5] = s; rs2[t >> 5] = s2; }
    __syncthreads();
    s = 0.f; s2 = 0.f;
#pragma unroll
    for (int i = 0; i < 8; i++) { s += rs[i]; s2 += rs2[i]; }
    float mu = s * (1.0f / Cc);
    float var = s2 * (1.0f / Cc) - mu * mu;
    float rstd = rsqrtf(var + 1e-5f);
    float dot = 0.f;
#pragma unroll
    for (int i = 0; i < 3; i++) {
        int c = t + i * 256;
        dot += ((v[i] - mu) * rstd * w[c] + b[c]) * wh[c];
    }
#pragma unroll
    for (int m = 16; m; m >>= 1) dot += __shfl_xor_sync(0xffffffffu, dot, m);
    if ((t & 31) == 0) rd[t >> 5] = dot;
    __syncthreads();
    if (t == 0) {
        float d = 0.f;
#pragma unroll
        for (int i = 0; i < 8; i++) d += rd[i];
        out[row] = d;
    }
}

// ---------------- host launch --------------------------------------------------
extern "C" void kernel_launch(void* const* d_in, const int* in_sizes, int n_in,
                              void* d_out, int out_size) {
    (void)in_sizes; (void)n_in; (void)out_size;
    const int*   idx   = (const int*)d_in[0];
    const float* wte   = (const float*)d_in[1];
    const float* wpe   = (const float*)d_in[2];
    const float* ln1w  = (const float*)d_in[3];
    const float* ln1b  = (const float*)d_in[4];
    const float* wqkv  = (const float*)d_in[5];
    const float* bqkv  = (const float*)d_in[6];
    const float* wao   = (const float*)d_in[7];
    const float* bao   = (const float*)d_in[8];
    const float* ln2w  = (const float*)d_in[9];
    const float* ln2b  = (const float*)d_in[10];
    const float* wfc   = (const float*)d_in[11];
    const float* bfc   = (const float*)d_in[12];
    const float* wfp   = (const float*)d_in[13];
    const float* bfp   = (const float*)d_in[14];
    const float* lnfw  = (const float*)d_in[15];
    const float* lnfb  = (const float*)d_in[16];
    const float* whead = (const float*)d_in[17];

    float* x;
    f16 *qkv16, *hh, *hl, *yh, *yl, *ffh, *ffl;
    f16 *wqkvT, *waoT, *wfcT, *wfpT;
    cudaGetSymbolAddress((void**)&x, g_x);
    cudaGetSymbolAddress((void**)&qkv16, g_qkv16);
    cudaGetSymbolAddress((void**)&hh, g_hh);
    cudaGetSymbolAddress((void**)&hl, g_hl);
    cudaGetSymbolAddress((void**)&yh, g_yh);
    cudaGetSymbolAddress((void**)&yl, g_yl);
    cudaGetSymbolAddress((void**)&ffh, g_ffh);
    cudaGetSymbolAddress((void**)&ffl, g_ffl);
    cudaGetSymbolAddress((void**)&wqkvT, g_wqkvT);
    cudaGetSymbolAddress((void**)&waoT, g_waoT);
    cudaGetSymbolAddress((void**)&wfcT, g_wfcT);
    cudaGetSymbolAddress((void**)&wfpT, g_wfpT);

    cudaFuncSetAttribute((const void*)attn16_kernel,
                         cudaFuncAttributeMaxDynamicSharedMemorySize, ATTN_SMEM);
    cudaFuncSetAttribute((const void*)gemm_mma<false, false, 1>,
                         cudaFuncAttributeMaxDynamicSharedMemorySize, GSM1);
    cudaFuncSetAttribute((const void*)gemm_mma<true, false, 2>,
                         cudaFuncAttributeMaxDynamicSharedMemorySize, GSM1);
    cudaFuncSetAttribute((const void*)gemm_mma96<false, true, 0>,
                         cudaFuncAttributeMaxDynamicSharedMemorySize, GSM9);

    wsplit_all<<<WS_ALL, 256>>>(wqkv, wao, wfc, wfp, wqkvT, waoT, wfcT, wfpT);

    embed_kernel<<<BT, 192>>>(idx, wte, wpe, x);

    for (int l = 0; l < Ll; l++) {
        ln_kernel<<<BT, 192>>>(x, ln1w + l * Cc, ln1b + l * Cc, hh, hl);
        gemm_mma<false, false, 1><<<dim3(18, 32), 256, GSM1>>>(
            hh, hl, wqkvT + (size_t)l * 3 * Cc * Cc, bqkv + l * 3 * Cc,
            nullptr, nullptr, qkv16, nullptr, BT, 3 * Cc, Cc);
        attn16_kernel<<<dim3(Tt / 128, Bq * Hh), 256, ATTN_SMEM>>>(qkv16, yh, yl);
        gemm_mma96<false, true, 0><<<dim3(8, 32), 256, GSM9>>>(
            yh, yl, waoT + (size_t)l * Cc * Cc, bao + l * Cc,
            x, x, nullptr, nullptr, BT, Cc, Cc);
        ln_kernel<<<BT, 192>>>(x, ln2w + l * Cc, ln2b + l * Cc, hh, hl);
        gemm_mma<true, false, 2><<<dim3(24, 32), 256, GSM1>>>(
            hh, hl, wfcT + (size_t)l * 4 * Cc * Cc, bfc + l * 4 * Cc,
            nullptr, nullptr, ffh, ffl, BT, 4 * Cc, Cc);
        gemm_mma96<false, true, 0><<<dim3(8, 32), 256, GSM9>>>(
            ffh, ffl, wfpT + (size_t)l * Cc * 4 * Cc, bfp + l * Cc,
            x, x, nullptr, nullptr, BT, Cc, 4 * Cc);
    }

    head_kernel<<<BT, 256>>>(x, lnfw, lnfb, whead, (float*)d_out);
}

// round 17
// speedup vs baseline: 1.0084x; 1.0056x over previous
#include <cuda_runtime.h>
#include <cuda_fp16.h>
#include <math.h>
#include <stdint.h>

#define Bq 4
#define Tt 1024
#define Cc 768
#define Hh 12
#define Dd 64
#define Ll 12
#define BT 4096

typedef __half f16;

// ---------------- scratch (device globals) ------------------------------------
__device__ __align__(16) float g_x[BT * Cc];
__device__ __align__(16) f16 g_qkv16[BT * 3 * Cc];

__device__ __align__(16) f16 g_hh[BT * Cc];
__device__ __align__(16) f16 g_hl[BT * Cc];
__device__ __align__(16) f16 g_yh[BT * Cc];
__device__ __align__(16) f16 g_yl[BT * Cc];
__device__ __align__(16) f16 g_ffh[BT * 4 * Cc];
__device__ __align__(16) f16 g_ffl[BT * 4 * Cc];

__device__ __align__(16) f16 g_wqkvT[Ll * 3 * Cc * Cc];
__device__ __align__(16) f16 g_waoT[Ll * Cc * Cc];
__device__ __align__(16) f16 g_wfcT[Ll * 4 * Cc * Cc];
__device__ __align__(16) f16 g_wfpT[Ll * Cc * 4 * Cc];

// ---------------- helpers -----------------------------------------------------
__device__ __forceinline__ uint32_t smem_u32(const void* p) {
    uint32_t a;
    asm("{ .reg .u64 t; cvta.to.shared.u64 t, %1; cvt.u32.u64 %0, t; }"
        : "=r"(a) : "l"(p));
    return a;
}
__device__ __forceinline__ void ldsm4(uint32_t* r, uint32_t addr) {
    asm volatile("ldmatrix.sync.aligned.m8n8.x4.shared.b16 {%0,%1,%2,%3}, [%4];"
                 : "=r"(r[0]), "=r"(r[1]), "=r"(r[2]), "=r"(r[3]) : "r"(addr));
}
__device__ __forceinline__ void ldsm4t(uint32_t* r, uint32_t addr) {
    asm volatile("ldmatrix.sync.aligned.m8n8.x4.trans.shared.b16 {%0,%1,%2,%3}, [%4];"
                 : "=r"(r[0]), "=r"(r[1]), "=r"(r[2]), "=r"(r[3]) : "r"(addr));
}
__device__ __forceinline__ void cp16(uint32_t dst, const void* src) {
    asm volatile("cp.async.ca.shared.global [%0], [%1], 16;"
                 :: "r"(dst), "l"(src) : "memory");
}
__device__ __forceinline__ void cp16b(uint32_t dst, const void* src) {
    asm volatile("cp.async.ca.shared.global.L2::256B [%0], [%1], 16;"
                 :: "r"(dst), "l"(src) : "memory");
}
__device__ __forceinline__ void cp_commit() {
    asm volatile("cp.async.commit_group;" ::: "memory");
}
__device__ __forceinline__ void mma16(float* c, const uint32_t* a,
                                      uint32_t b0, uint32_t b1) {
    asm volatile(
        "mma.sync.aligned.m16n8k16.row.col.f32.f16.f16.f32 "
        "{%0,%1,%2,%3}, {%4,%5,%6,%7}, {%8,%9}, {%0,%1,%2,%3};"
        : "+f"(c[0]), "+f"(c[1]), "+f"(c[2]), "+f"(c[3])
        : "r"(a[0]), "r"(a[1]), "r"(a[2]), "r"(a[3]), "r"(b0), "r"(b1));
}
__device__ __forceinline__ void split2(float f, f16& h, f16& l) {
    h = __float2half_rn(f);
    l = __float2half_rn(f - __half2float(h));
}
__device__ __forceinline__ float gelu_f(float x) {
    float x3 = x * x * x;
    return 0.5f * x * (1.f + tanhf(0.7978845608028654f * (x + 0.044715f * x3)));
}
__device__ __forceinline__ uint32_t packh2(float a, float b) {
    __half2 h = __floats2half2_rn(a, b);
    return *(uint32_t*)&h;
}

// ---------------- weight transpose to fp16 (all 4 weights, one launch) ---------
#define WS_QKV 20736
#define WS_AO  (WS_QKV + 6912)
#define WS_FC  (WS_AO + 27648)
#define WS_ALL (WS_FC + 27648)

__global__ void wsplit_all(const float* __restrict__ wqkv, const float* __restrict__ wao,
                           const float* __restrict__ wfc, const float* __restrict__ wfp,
                           f16* __restrict__ tqkv, f16* __restrict__ tao,
                           f16* __restrict__ tfc, f16* __restrict__ tfp) {
    __shared__ float t[32][33];
    int bid = blockIdx.x;
    const float* W;
    f16* T;
    int K, N, nx, base;
    if (bid < WS_QKV)     { W = wqkv; T = tqkv; K = Cc;     N = 3 * Cc; nx = 72; base = bid; }
    else if (bid < WS_AO) { W = wao;  T = tao;  K = Cc;     N = Cc;     nx = 24; base = bid - WS_QKV; }
    else if (bid < WS_FC) { W = wfc;  T = tfc;  K = Cc;     N = 4 * Cc; nx = 96; base = bid - WS_AO; }
    else                  { W = wfp;  T = tfp;  K = 4 * Cc; N = Cc;     nx = 24; base = bid - WS_FC; }
    int per_layer = nx * (K >> 5);
    int layer = base / per_layer;
    int rem = base - layer * per_layer;
    int bx = rem % nx, by = rem / nx;
    size_t loff = (size_t)layer * K * N;
    const float* Wl = W + loff;
    f16* Tl = T + loff;
    int n0 = bx * 32, k0 = by * 32;
    int tx = threadIdx.x & 31, ty = threadIdx.x >> 5;
#pragma unroll
    for (int j = 0; j < 4; j++)
        t[ty + 8 * j][tx] = Wl[(size_t)(k0 + ty + 8 * j) * N + n0 + tx];
    __syncthreads();
#pragma unroll
    for (int j = 0; j < 4; j++) {
        int nr = ty + 8 * j;
        Tl[(size_t)(n0 + nr) * K + k0 + tx] = __float2half_rn(t[tx][nr]);
    }
}

// ---------------- embedding ---------------------------------------------------
__global__ void embed_kernel(const int* __restrict__ idx, const float* __restrict__ wte,
                             const float* __restrict__ wpe, float* __restrict__ x) {
    int row = blockIdx.x;
    int tok = idx[row];
    int t = row & (Tt - 1);
    int c = threadIdx.x * 4;
    float4 a = *(const float4*)(wte + (size_t)tok * Cc + c);
    float4 p = *(const float4*)(wpe + (size_t)t * Cc + c);
    a.x += p.x; a.y += p.y; a.z += p.z; a.w += p.w;
    *(float4*)(x + (size_t)row * Cc + c) = a;
}

// ---------------- layernorm (fp32 in, hi/lo fp16 out) -- 192 thr, float4 -------
__global__ void ln_kernel(const float* __restrict__ in, const float* __restrict__ w,
                          const float* __restrict__ b, f16* __restrict__ oh,
                          f16* __restrict__ ol) {
    int row = blockIdx.x;
    int t = threadIdx.x;   // 0..191
    float4 v = *(const float4*)(in + (size_t)row * Cc + t * 4);
    float s = v.x + v.y + v.z + v.w;
    float s2 = v.x * v.x + v.y * v.y + v.z * v.z + v.w * v.w;
#pragma unroll
    for (int m = 16; m; m >>= 1) {
        s  += __shfl_xor_sync(0xffffffffu, s, m);
        s2 += __shfl_xor_sync(0xffffffffu, s2, m);
    }
    __shared__ float rs[6], rs2[6];
    if ((t & 31) == 0) { rs[t >> 5] = s; rs2[t >> 5] = s2; }
    __syncthreads();
    s = 0.f; s2 = 0.f;
#pragma unroll
    for (int i = 0; i < 6; i++) { s += rs[i]; s2 += rs2[i]; }
    float mu = s * (1.0f / Cc);
    float var = s2 * (1.0f / Cc) - mu * mu;
    float rstd = rsqrtf(var + 1e-5f);
    float4 wv = *(const float4*)(w + t * 4);
    float4 bv = *(const float4*)(b + t * 4);
    float o0 = (v.x - mu) * rstd * wv.x + bv.x;
    float o1 = (v.y - mu) * rstd * wv.y + bv.y;
    float o2 = (v.z - mu) * rstd * wv.z + bv.z;
    float o3 = (v.w - mu) * rstd * wv.w + bv.w;
    f16 h0, l0, h1, l1, h2, l2, h3, l3;
    split2(o0, h0, l0); split2(o1, h1, l1); split2(o2, h2, l2); split2(o3, h3, l3);
    __half2 hA, hB, lA, lB;
    hA.x = h0; hA.y = h1; hB.x = h2; hB.y = h3;
    lA.x = l0; lA.y = l1; lB.x = l2; lB.y = l3;
    size_t off = (size_t)row * Cc + t * 4;
    *(__half2*)(oh + off) = hA;
    *(__half2*)(oh + off + 2) = hB;
    *(__half2*)(ol + off) = lA;
    *(__half2*)(ol + off + 2) = lB;
}

// ---------------- shared GEMM pieces -------------------------------------------
#define SAW 20

template <bool GELU, bool RES, int OUTM, int NJ>
__device__ __forceinline__ void gemm_epilogue(
    float acc[2][2 * NJ][4], int m0, int n0, int wm, int wn, int g, int c,
    const float* __restrict__ bias, const float* __restrict__ res,
    float* __restrict__ outf, f16* __restrict__ outh, f16* __restrict__ outl, int N) {
#pragma unroll
    for (int mt = 0; mt < 2; mt++) {
        int rbase = m0 + wm * 32 + mt * 16 + g;
#pragma unroll
        for (int nt = 0; nt < 2 * NJ; nt++) {
            int col = n0 + wn * (NJ * 16) + nt * 8 + 2 * c;
            float b0v = bias[col], b1v = bias[col + 1];
#pragma unroll
            for (int rr = 0; rr < 2; rr++) {
                int r = rbase + rr * 8;
                float v0 = acc[mt][nt][rr * 2 + 0] + b0v;
                float v1 = acc[mt][nt][rr * 2 + 1] + b1v;
                if (GELU) { v0 = gelu_f(v0); v1 = gelu_f(v1); }
                if (RES) {
                    float2 rv = *(const float2*)(res + (size_t)r * N + col);
                    v0 += rv.x;
                    v1 += rv.y;
                }
                if (OUTM == 0) {
                    float2 ov; ov.x = v0; ov.y = v1;
                    *(float2*)(outf + (size_t)r * N + col) = ov;
                } else if (OUTM == 1) {
                    uint32_t hv = packh2(v0, v1);
                    *(uint32_t*)(outh + (size_t)r * N + col) = hv;
                } else {
                    f16 h0, l0, h1, l1;
                    split2(v0, h0, l0);
                    split2(v1, h1, l1);
                    __half2 hv; hv.x = h0; hv.y = h1;
                    __half2 lv; lv.x = l0; lv.y = l1;
                    *(__half2*)(outh + (size_t)r * N + col) = hv;
                    *(__half2*)(outl + (size_t)r * N + col) = lv;
                }
            }
        }
    }
}

// one k-tile; B-fragments pipelined one jj ahead (R14-proven) AND MMAs batched
// ah-group then al-group: per-accumulator order unchanged (ah before al) ->
// bit-identical numerics, RAW distance 4 on each accumulator.
template <int NJ>
__device__ __forceinline__ void gemm_ktile(
    float acc[2][2 * NJ][4], uint32_t abase, uint32_t bbase, uint32_t offAL) {
#pragma unroll
    for (int ks = 0; ks < 2; ks++) {
        uint32_t ah[2][4], al[2][4];
#pragma unroll
        for (int mt = 0; mt < 2; mt++) {
            uint32_t ar = abase + (uint32_t)(mt * 16) * SAW * 4 + ks * 32;
            ldsm4(ah[mt], ar);
            ldsm4(al[mt], ar + offAL);
        }
        uint32_t bf[4];
        ldsm4(bf, bbase + ks * 32);
#pragma unroll
        for (int jj = 0; jj < NJ; jj++) {
            uint32_t bfn[4];
            if (jj + 1 < NJ)
                ldsm4(bfn, bbase + (uint32_t)((jj + 1) * 16) * SAW * 4 + ks * 32);
            mma16(acc[0][2 * jj], ah[0], bf[0], bf[1]);
            mma16(acc[1][2 * jj], ah[1], bf[0], bf[1]);
            mma16(acc[0][2 * jj + 1], ah[0], bf[2], bf[3]);
            mma16(acc[1][2 * jj + 1], ah[1], bf[2], bf[3]);
            mma16(acc[0][2 * jj], al[0], bf[0], bf[1]);
            mma16(acc[1][2 * jj], al[1], bf[0], bf[1]);
            mma16(acc[0][2 * jj + 1], al[0], bf[2], bf[3]);
            mma16(acc[1][2 * jj + 1], al[1], bf[2], bf[3]);
            if (jj + 1 < NJ) {
                bf[0] = bfn[0]; bf[1] = bfn[1]; bf[2] = bfn[2]; bf[3] = bfn[3];
            }
        }
    }
}

// ---------------- GEMM 128x128 (256 thr, 3-stage) ------------------------------
#define OFF_AL1 10240u
#define OFF_B1  20480u
#define BUFSZ1  30720u
#define GSM1    (3 * 30720)

template <bool GELU, bool RES, int OUTM>
__global__ void __launch_bounds__(256, 2) gemm_mma(
    const f16* __restrict__ Ah, const f16* __restrict__ Al,
    const f16* __restrict__ B,
    const float* __restrict__ bias, const float* __restrict__ res,
    float* __restrict__ outf, f16* __restrict__ outh, f16* __restrict__ outl,
    int M, int N, int K) {
    extern __shared__ char smem[];
    const uint32_t sb = smem_u32(smem);
    const int tid = threadIdx.x;
    const int lane = tid & 31, wid = tid >> 5;
    const int g = lane >> 2, c = lane & 3;
    const int wm = wid & 3, wn = wid >> 2;
    const int m0 = blockIdx.y * 128, n0 = blockIdx.x * 128;

    const int r_ld = tid >> 2;
    const int q_ld = tid & 3;
    const uint32_t d0 = (uint32_t)(r_ld * SAW + q_ld * 4) * 4;
    const uint32_t d1 = (uint32_t)((r_ld + 64) * SAW + q_ld * 4) * 4;

    const int tl = lane >> 3, rw = lane & 7;
    const uint32_t aoff = (uint32_t)(((tl & 1) * 8 + rw) * SAW * 4 + (tl >> 1) * 16);
    const uint32_t boff = (uint32_t)(((tl >> 1) * 8 + rw) * SAW * 4 + (tl & 1) * 16);

    float acc[2][8][4];
#pragma unroll
    for (int mt = 0; mt < 2; mt++)
#pragma unroll
        for (int nt = 0; nt < 8; nt++)
#pragma unroll
            for (int r = 0; r < 4; r++) acc[mt][nt][r] = 0.f;

    const int nkt = K >> 5;

#define ISSUE1(KT, BUF)                                                         \
    do {                                                                        \
        uint32_t bs = sb + (BUF) * BUFSZ1;                                      \
        size_t ka = (size_t)(m0 + r_ld) * K + (KT) * 32 + q_ld * 8;             \
        size_t kb = (size_t)(n0 + r_ld) * K + (KT) * 32 + q_ld * 8;             \
        cp16(bs + d0, Ah + ka);                                                 \
        cp16(bs + d1, Ah + ka + (size_t)64 * K);                                \
        cp16(bs + OFF_AL1 + d0, Al + ka);                                       \
        cp16(bs + OFF_AL1 + d1, Al + ka + (size_t)64 * K);                      \
        cp16b(bs + OFF_B1 + d0, B + kb);                                        \
        cp16b(bs + OFF_B1 + d1, B + kb + (size_t)64 * K);                       \
        cp_commit();                                                            \
    } while (0)

    ISSUE1(0, 0);
    ISSUE1(1, 1);

    for (int kt = 0; kt < nkt; kt++) {
        if (kt + 1 < nkt)
            asm volatile("cp.async.wait_group 1;" ::: "memory");
        else
            asm volatile("cp.async.wait_group 0;" ::: "memory");
        __syncthreads();
        if (kt + 2 < nkt) ISSUE1(kt + 2, (kt + 2) % 3);

        uint32_t bs = sb + (uint32_t)(kt % 3) * BUFSZ1;
        uint32_t abase = bs + aoff + (uint32_t)(wm * 32) * SAW * 4;
        uint32_t bbase = bs + OFF_B1 + boff + (uint32_t)(wn * 64) * SAW * 4;
        gemm_ktile<4>(acc, abase, bbase, OFF_AL1);
    }

    gemm_epilogue<GELU, RES, OUTM, 4>(acc, m0, n0, wm, wn, g, c, bias, res,
                                      outf, outh, outl, N);
}

// ---------------- GEMM 128x96 (256 thr, 3-stage) -- for N=768 GEMMs -------------
#define OFF_AL9 10240u
#define OFF_B9  20480u
#define BUFSZ9  28160u
#define GSM9    (3 * 28160)

template <bool GELU, bool RES, int OUTM>
__global__ void __launch_bounds__(256, 2) gemm_mma96(
    const f16* __restrict__ Ah, const f16* __restrict__ Al,
    const f16* __restrict__ B,
    const float* __restrict__ bias, const float* __restrict__ res,
    float* __restrict__ outf, f16* __restrict__ outh, f16* __restrict__ outl,
    int M, int N, int K) {
    extern __shared__ char smem[];
    const uint32_t sb = smem_u32(smem);
    const int tid = threadIdx.x;
    const int lane = tid & 31, wid = tid >> 5;
    const int g = lane >> 2, c = lane & 3;
    const int wm = wid & 3, wn = wid >> 2;
    const int m0 = blockIdx.y * 128, n0 = blockIdx.x * 96;

    const int r_ld = tid >> 2;
    const int q_ld = tid & 3;
    const uint32_t d0 = (uint32_t)(r_ld * SAW + q_ld * 4) * 4;
    const uint32_t d1 = (uint32_t)((r_ld + 64) * SAW + q_ld * 4) * 4;
    const int rb1 = tid >> 2, qb1 = tid & 3;
    const int t2 = tid + 256;
    const int rb2 = t2 >> 2, qb2v = t2 & 3;
    const uint32_t db1 = (uint32_t)(rb1 * SAW + qb1 * 4) * 4;
    const uint32_t db2 = (uint32_t)(rb2 * SAW + qb2v * 4) * 4;
    const bool doB2 = (tid < 128);

    const int tl = lane >> 3, rw = lane & 7;
    const uint32_t aoff = (uint32_t)(((tl & 1) * 8 + rw) * SAW * 4 + (tl >> 1) * 16);
    const uint32_t boff = (uint32_t)(((tl >> 1) * 8 + rw) * SAW * 4 + (tl & 1) * 16);

    float acc[2][6][4];
#pragma unroll
    for (int mt = 0; mt < 2; mt++)
#pragma unroll
        for (int nt = 0; nt < 6; nt++)
#pragma unroll
            for (int r = 0; r < 4; r++) acc[mt][nt][r] = 0.f;

    const int nkt = K >> 5;

#define ISSUE9(KT, BUF)                                                         \
    do {                                                                        \
        uint32_t bs = sb + (BUF) * BUFSZ9;                                      \
        size_t ka = (size_t)(m0 + r_ld) * K + (KT) * 32 + q_ld * 8;             \
        cp16(bs + d0, Ah + ka);                                                 \
        cp16(bs + d1, Ah + ka + (size_t)64 * K);                                \
        cp16(bs + OFF_AL9 + d0, Al + ka);                                       \
        cp16(bs + OFF_AL9 + d1, Al + ka + (size_t)64 * K);                      \
        size_t kb = (size_t)(n0 + rb1) * K + (KT) * 32 + qb1 * 8;               \
        cp16b(bs + OFF_B9 + db1, B + kb);                                       \
        if (doB2) {                                                             \
            size_t kb2 = (size_t)(n0 + rb2) * K + (KT) * 32 + qb2v * 8;         \
            cp16b(bs + OFF_B9 + db2, B + kb2);                                  \
        }                                                                       \
        cp_commit();                                                            \
    } while (0)

    ISSUE9(0, 0);
    ISSUE9(1, 1);

    for (int kt = 0; kt < nkt; kt++) {
        if (kt + 1 < nkt)
            asm volatile("cp.async.wait_group 1;" ::: "memory");
        else
            asm volatile("cp.async.wait_group 0;" ::: "memory");
        __syncthreads();
        if (kt + 2 < nkt) ISSUE9(kt + 2, (kt + 2) % 3);

        uint32_t bs = sb + (uint32_t)(kt % 3) * BUFSZ9;
        uint32_t abase = bs + aoff + (uint32_t)(wm * 32) * SAW * 4;
        uint32_t bbase = bs + OFF_B9 + boff + (uint32_t)(wn * 48) * SAW * 4;
        gemm_ktile<3>(acc, abase, bbase, OFF_AL9);
    }

    gemm_epilogue<GELU, RES, OUTM, 3>(acc, m0, n0, wm, wn, g, c, bias, res,
                                      outf, outh, outl, N);
}

// ---------------- flash attention: 3-stage cp.async K/V, pipelined fragments ---
#define QSZ (128 * 72)
#define KVSTG (2 * 64 * 72)
#define ATTN_SMEM ((QSZ + 3 * KVSTG) * 2)   // 73728 B

__global__ void __launch_bounds__(256) attn16_kernel(const f16* __restrict__ qkv,
                                                     f16* __restrict__ yh,
                                                     f16* __restrict__ yl) {
    extern __shared__ f16 sh[];
    const uint32_t sQa = smem_u32(sh);

    const int qb = gridDim.x - 1 - blockIdx.x;   // longest CTAs first
    const int b = blockIdx.y / Hh, h = blockIdx.y % Hh;
    const int tid = threadIdx.x, lane = tid & 31, wid = tid >> 5;
    const int g = lane >> 2, c = lane & 3;
    const int tl = lane >> 3, rw = lane & 7;
    const f16* base = qkv + (size_t)b * Tt * (3 * Cc) + h * Dd;

    const uint32_t aoff = (uint32_t)(((tl & 1) * 8 + rw) * 72 + (tl >> 1) * 8) * 2;
    const uint32_t boff = (uint32_t)(((tl >> 1) * 8 + rw) * 72 + (tl & 1) * 8) * 2;

#pragma unroll
    for (int l = 0; l < 4; l++) {
        int ch = tid + l * 256;
        int r = ch >> 3, c8 = ch & 7;
        cp16(sQa + (uint32_t)(r * 72 + c8 * 8) * 2,
             base + (size_t)(qb * 128 + r) * (3 * Cc) + c8 * 8);
    }
    cp_commit();

    const int kbmax = 2 * qb + 1;

#define SKB(S) (sQa + (uint32_t)(QSZ + (S) * KVSTG) * 2)
#define SVB(S) (sQa + (uint32_t)(QSZ + (S) * KVSTG + 64 * 72) * 2)

#define ISSUEKV(KB, S)                                                          \
    do {                                                                        \
        uint32_t kk = SKB(S), vv = SVB(S);                                      \
        _Pragma("unroll")                                                       \
        for (int l = 0; l < 2; l++) {                                           \
            int ch = tid + l * 256;                                             \
            int r = ch >> 3, c8 = ch & 7;                                       \
            uint32_t so = (uint32_t)(r * 72 + c8 * 8) * 2;                      \
            const f16* gp = base + (size_t)((KB) * 64 + r) * (3 * Cc) + c8 * 8; \
            cp16(kk + so, gp + Cc);                                             \
            cp16(vv + so, gp + 2 * Cc);                                         \
        }                                                                       \
        cp_commit();                                                            \
    } while (0)

    ISSUEKV(0, 0);
    ISSUEKV(1, 1);

    asm volatile("cp.async.wait_group 2;" ::: "memory");  // Q done
    __syncthreads();

    uint32_t qf[4][4];
    {
        uint32_t qa = sQa + (uint32_t)(wid * 16) * 144 + aoff;
#pragma unroll
        for (int t = 0; t < 4; t++) ldsm4(qf[t], qa + t * 32);
    }

    float o[8][4];
#pragma unroll
    for (int j = 0; j < 8; j++)
#pragma unroll
        for (int r = 0; r < 4; r++) o[j][r] = 0.f;
    float mi0 = -1e30f, mi1 = -1e30f, li0 = 0.f, li1 = 0.f;
    const int row0 = qb * 128 + wid * 16 + g;
    const int row1 = row0 + 8;
    const int wqmax = qb * 128 + wid * 16 + 15;

    for (int kb = 0; kb <= kbmax; kb++) {
        if (kb + 1 <= kbmax)
            asm volatile("cp.async.wait_group 1;" ::: "memory");
        else
            asm volatile("cp.async.wait_group 0;" ::: "memory");
        __syncthreads();
        if (kb + 2 <= kbmax) ISSUEKV(kb + 2, (kb + 2) % 3);

        uint32_t sK = SKB(kb % 3), sV = SVB(kb % 3);

        if (kb * 64 <= wqmax) {
            float s[8][4];
#pragma unroll
            for (int j = 0; j < 8; j++)
#pragma unroll
                for (int r = 0; r < 4; r++) s[j][r] = 0.f;
            {
                uint32_t kf[4];
                ldsm4(kf, sK + boff);
#pragma unroll
                for (int jj = 0; jj < 4; jj++) {
                    uint32_t kbse = sK + boff + (uint32_t)(jj * 16) * 144;
#pragma unroll
                    for (int t = 0; t < 4; t++) {
                        uint32_t kfn[4];
                        if (t + 1 < 4)
                            ldsm4(kfn, kbse + (t + 1) * 32);
                        else if (jj + 1 < 4)
                            ldsm4(kfn, sK + boff + (uint32_t)((jj + 1) * 16) * 144);
                        mma16(s[2 * jj], qf[t], kf[0], kf[1]);
                        mma16(s[2 * jj + 1], qf[t], kf[2], kf[3]);
                        if (t + 1 < 4 || jj + 1 < 4) {
                            kf[0] = kfn[0]; kf[1] = kfn[1];
                            kf[2] = kfn[2]; kf[3] = kfn[3];
                        }
                    }
                }
            }
            const bool doMask = (kb * 64 + 63) > (qb * 128 + wid * 16);
#pragma unroll
            for (int j = 0; j < 8; j++) {
                int col = kb * 64 + 8 * j + 2 * c;
                s[j][0] *= 0.125f; s[j][1] *= 0.125f;
                s[j][2] *= 0.125f; s[j][3] *= 0.125f;
                if (doMask) {
                    if (col > row0) s[j][0] = -1e30f;
                    if (col + 1 > row0) s[j][1] = -1e30f;
                    if (col > row1) s[j][2] = -1e30f;
                    if (col + 1 > row1) s[j][3] = -1e30f;
                }
            }
            float rm0 = -1e30f, rm1 = -1e30f;
#pragma unroll
            for (int j = 0; j < 8; j++) {
                rm0 = fmaxf(rm0, fmaxf(s[j][0], s[j][1]));
                rm1 = fmaxf(rm1, fmaxf(s[j][2], s[j][3]));
            }
            rm0 = fmaxf(rm0, __shfl_xor_sync(0xffffffffu, rm0, 1));
            rm0 = fmaxf(rm0, __shfl_xor_sync(0xffffffffu, rm0, 2));
            rm1 = fmaxf(rm1, __shfl_xor_sync(0xffffffffu, rm1, 1));
            rm1 = fmaxf(rm1, __shfl_xor_sync(0xffffffffu, rm1, 2));
            float mn0 = fmaxf(mi0, rm0), mn1 = fmaxf(mi1, rm1);
            float al0 = __expf(mi0 - mn0), al1 = __expf(mi1 - mn1);
            float rs0 = 0.f, rs1 = 0.f;
#pragma unroll
            for (int j = 0; j < 8; j++) {
                s[j][0] = __expf(s[j][0] - mn0);
                s[j][1] = __expf(s[j][1] - mn0);
                s[j][2] = __expf(s[j][2] - mn1);
                s[j][3] = __expf(s[j][3] - mn1);
                rs0 += s[j][0] + s[j][1];
                rs1 += s[j][2] + s[j][3];
            }
            rs0 += __shfl_xor_sync(0xffffffffu, rs0, 1);
            rs0 += __shfl_xor_sync(0xffffffffu, rs0, 2);
            rs1 += __shfl_xor_sync(0xffffffffu, rs1, 1);
            rs1 += __shfl_xor_sync(0xffffffffu, rs1, 2);
            li0 = li0 * al0 + rs0;
            li1 = li1 * al1 + rs1;
            mi0 = mn0; mi1 = mn1;
#pragma unroll
            for (int j = 0; j < 8; j++) {
                o[j][0] *= al0; o[j][1] *= al0;
                o[j][2] *= al1; o[j][3] *= al1;
            }
            uint32_t pa[4][4];
#pragma unroll
            for (int t = 0; t < 4; t++) {
                pa[t][0] = packh2(s[2 * t][0], s[2 * t][1]);
                pa[t][1] = packh2(s[2 * t][2], s[2 * t][3]);
                pa[t][2] = packh2(s[2 * t + 1][0], s[2 * t + 1][1]);
                pa[t][3] = packh2(s[2 * t + 1][2], s[2 * t + 1][3]);
            }
            {
                uint32_t vf[4];
                ldsm4t(vf, sV + aoff);
#pragma unroll
                for (int jj = 0; jj < 4; jj++) {
#pragma unroll
                    for (int t = 0; t < 4; t++) {
                        uint32_t vfn[4];
                        if (t + 1 < 4)
                            ldsm4t(vfn, sV + aoff + (uint32_t)((t + 1) * 16) * 144 + jj * 32);
                        else if (jj + 1 < 4)
                            ldsm4t(vfn, sV + aoff + (jj + 1) * 32);
                        mma16(o[2 * jj], pa[t], vf[0], vf[1]);
                        mma16(o[2 * jj + 1], pa[t], vf[2], vf[3]);
                        if (t + 1 < 4 || jj + 1 < 4) {
                            vf[0] = vfn[0]; vf[1] = vfn[1];
                            vf[2] = vfn[2]; vf[3] = vfn[3];
                        }
                    }
                }
            }
        }
    }

    float inv0 = 1.f / li0, inv1 = 1.f / li1;
    size_t rb0 = ((size_t)b * Tt + qb * 128 + wid * 16 + g) * Cc + h * Dd;
    size_t rb1 = rb0 + (size_t)8 * Cc;
#pragma unroll
    for (int j = 0; j < 8; j++) {
        int col = 8 * j + 2 * c;
        f16 h0, l0, h1, l1;
        split2(o[j][0] * inv0, h0, l0);
        split2(o[j][1] * inv0, h1, l1);
        __half2 hv; hv.x = h0; hv.y = h1;
        __half2 lv; lv.x = l0; lv.y = l1;
        *(__half2*)(yh + rb0 + col) = hv;
        *(__half2*)(yl + rb0 + col) = lv;
        split2(o[j][2] * inv1, h0, l0);
        split2(o[j][3] * inv1, h1, l1);
        hv.x = h0; hv.y = h1;
        lv.x = l0; lv.y = l1;
        *(__half2*)(yh + rb1 + col) = hv;
        *(__half2*)(yl + rb1 + col) = lv;
    }
}

// ---------------- final LN + head matvec --------------------------------------
__global__ void head_kernel(const float* __restrict__ x, const float* __restrict__ w,
                            const float* __restrict__ b, const float* __restrict__ wh,
                            float* __restrict__ out) {
    int row = blockIdx.x;
    int t = threadIdx.x;
    const float* xr = x + (size_t)row * Cc;
    float v[3];
    float s = 0.f, s2 = 0.f;
#pragma unroll
    for (int i = 0; i < 3; i++) { v[i] = xr[t + i * 256]; s += v[i]; s2 += v[i] * v[i]; }
#pragma unroll
    for (int m = 16; m; m >>= 1) {
        s  += __shfl_xor_sync(0xffffffffu, s, m);
        s2 += __shfl_xor_sync(0xffffffffu, s2, m);
    }
    __shared__ float rs[8], rs2[8], rd[8];
    if ((t & 31) == 0) { rs[t >> 5] = s; rs2[t >> 5] = s2; }
    __syncthreads();
    s = 0.f; s2 = 0.f;
#pragma unroll
    for (int i = 0; i < 8; i++) { s += rs[i]; s2 += rs2[i]; }
    float mu = s * (1.0f / Cc);
    float var = s2 * (1.0f / Cc) - mu * mu;
    float rstd = rsqrtf(var + 1e-5f);
    float dot = 0.f;
#pragma unroll
    for (int i = 0; i < 3; i++) {
        int c = t + i * 256;
        dot += ((v[i] - mu) * rstd * w[c] + b[c]) * wh[c];
    }
#pragma unroll
    for (int m = 16; m; m >>= 1) dot += __shfl_xor_sync(0xffffffffu, dot, m);
    if ((t & 31) == 0) rd[t >> 5] = dot;
    __syncthreads();
    if (t == 0) {
        float d = 0.f;
#pragma unroll
        for (int i = 0; i < 8; i++) d += rd[i];
        out[row] = d;
    }
}

// ---------------- host launch --------------------------------------------------
extern "C" void kernel_launch(void* const* d_in, const int* in_sizes, int n_in,
                              void* d_out, int out_size) {
    (void)in_sizes; (void)n_in; (void)out_size;
    const int*   idx   = (const int*)d_in[0];
    const float* wte   = (const float*)d_in[1];
    const float* wpe   = (const float*)d_in[2];
    const float* ln1w  = (const float*)d_in[3];
    const float* ln1b  = (const float*)d_in[4];
    const float* wqkv  = (const float*)d_in[5];
    const float* bqkv  = (const float*)d_in[6];
    const float* wao   = (const float*)d_in[7];
    const float* bao   = (const float*)d_in[8];
    const float* ln2w  = (const float*)d_in[9];
    const float* ln2b  = (const float*)d_in[10];
    const float* wfc   = (const float*)d_in[11];
    const float* bfc   = (const float*)d_in[12];
    const float* wfp   = (const float*)d_in[13];
    const float* bfp   = (const float*)d_in[14];
    const float* lnfw  = (const float*)d_in[15];
    const float* lnfb  = (const float*)d_in[16];
    const float* whead = (const float*)d_in[17];

    float* x;
    f16 *qkv16, *hh, *hl, *yh, *yl, *ffh, *ffl;
    f16 *wqkvT, *waoT, *wfcT, *wfpT;
    cudaGetSymbolAddress((void**)&x, g_x);
    cudaGetSymbolAddress((void**)&qkv16, g_qkv16);
    cudaGetSymbolAddress((void**)&hh, g_hh);
    cudaGetSymbolAddress((void**)&hl, g_hl);
    cudaGetSymbolAddress((void**)&yh, g_yh);
    cudaGetSymbolAddress((void**)&yl, g_yl);
    cudaGetSymbolAddress((void**)&ffh, g_ffh);
    cudaGetSymbolAddress((void**)&ffl, g_ffl);
    cudaGetSymbolAddress((void**)&wqkvT, g_wqkvT);
    cudaGetSymbolAddress((void**)&waoT, g_waoT);
    cudaGetSymbolAddress((void**)&wfcT, g_wfcT);
    cudaGetSymbolAddress((void**)&wfpT, g_wfpT);

    cudaFuncSetAttribute((const void*)attn16_kernel,
                         cudaFuncAttributeMaxDynamicSharedMemorySize, ATTN_SMEM);
    cudaFuncSetAttribute((const void*)gemm_mma<false, false, 1>,
                         cudaFuncAttributeMaxDynamicSharedMemorySize, GSM1);
    cudaFuncSetAttribute((const void*)gemm_mma<true, false, 2>,
                         cudaFuncAttributeMaxDynamicSharedMemorySize, GSM1);
    cudaFuncSetAttribute((const void*)gemm_mma96<false, true, 0>,
                         cudaFuncAttributeMaxDynamicSharedMemorySize, GSM9);

    wsplit_all<<<WS_ALL, 256>>>(wqkv, wao, wfc, wfp, wqkvT, waoT, wfcT, wfpT);

    embed_kernel<<<BT, 192>>>(idx, wte, wpe, x);

    for (int l = 0; l < Ll; l++) {
        ln_kernel<<<BT, 192>>>(x, ln1w + l * Cc, ln1b + l * Cc, hh, hl);
        gemm_mma<false, false, 1><<<dim3(18, 32), 256, GSM1>>>(
            hh, hl, wqkvT + (size_t)l * 3 * Cc * Cc, bqkv + l * 3 * Cc,
            nullptr, nullptr, qkv16, nullptr, BT, 3 * Cc, Cc);
        attn16_kernel<<<dim3(Tt / 128, Bq * Hh), 256, ATTN_SMEM>>>(qkv16, yh, yl);
        gemm_mma96<false, true, 0><<<dim3(8, 32), 256, GSM9>>>(
            yh, yl, waoT + (size_t)l * Cc * Cc, bao + l * Cc,
            x, x, nullptr, nullptr, BT, Cc, Cc);
        ln_kernel<<<BT, 192>>>(x, ln2w + l * Cc, ln2b + l * Cc, hh, hl);
        gemm_mma<true, false, 2><<<dim3(24, 32), 256, GSM1>>>(
            hh, hl, wfcT + (size_t)l * 4 * Cc * Cc, bfc + l * 4 * Cc,
            nullptr, nullptr, ffh, ffl, BT, 4 * Cc, Cc);
        gemm_mma96<false, true, 0><<<dim3(8, 32), 256, GSM9>>>(
            ffh, ffl, wfpT + (size_t)l * Cc * 4 * Cc, bfp + l * Cc,
            x, x, nullptr, nullptr, BT, Cc, 4 * Cc);
    }

    head_kernel<<<BT, 256>>>(x, lnfw, lnfb, whead, (float*)d_out);
}